// round 13
// baseline (speedup 1.0000x reference)
#include <cuda_runtime.h>
#include <math.h>

// ---------------------------------------------------------------------------
// HawkeyeMoE: H=1024, E=4, L=2, NH=16, DH=64, B=8, S=512, HF=2816, KEEP=30
// Full fp32 pipeline. GEMMs use packed fma.rn.f32x2 (sm_100+).
// ---------------------------------------------------------------------------
#define NTOK 4096
#define HD   1024
#define HF   2816
#define NKEEP 240

// ----------------------------- scratch buffers -----------------------------
__device__ float g_X [NTOK*HD];
__device__ float g_R [NTOK*4];
__device__ float g_H [NTOK*HD];
__device__ float g_H2[NTOK*HD];
__device__ float g_XN[NTOK*HD];
__device__ float g_Q [NTOK*HD];
__device__ float g_K [NTOK*HD];
__device__ float g_V [NTOK*HD];
__device__ float g_O [NTOK*HD];
__device__ float g_U [NTOK*HF];
__device__ float g_T [NTOK*HF];
__device__ float g_cXN[NKEEP*HD];
__device__ float g_cH [NKEEP*HD];
__device__ float g_cQ [NKEEP*HD];
__device__ float g_cO [NKEEP*HD];
__device__ float g_cH2[NKEEP*HD];
__device__ float g_cU [NKEEP*HF];
__device__ float g_cT [NKEEP*HF];
__device__ float g_cF [NKEEP*HD];
__device__ float g_C  [NKEEP*HD];
__device__ float g_Y  [NKEEP*HD];

// ----------------------------- helpers -------------------------------------
union F2U { float2 f; unsigned long long u; };

__device__ __forceinline__ unsigned long long pk2(float x){
  F2U c; c.f = make_float2(x, x); return c.u;
}
__device__ __forceinline__ void ffma2(unsigned long long &c, unsigned long long a, unsigned long long b){
  asm("fma.rn.f32x2 %0, %1, %2, %0;" : "+l"(c) : "l"(a), "l"(b));
}

__device__ __forceinline__ float blockReduceSum(float v, float* sm){
  int lane = threadIdx.x & 31, warp = threadIdx.x >> 5;
  #pragma unroll
  for (int o=16;o;o>>=1) v += __shfl_down_sync(0xffffffffu, v, o);
  if (!lane) sm[warp] = v;
  __syncthreads();
  if (warp == 0){
    float w = (lane < (int)(blockDim.x >> 5)) ? sm[lane] : 0.f;
    #pragma unroll
    for (int o=16;o;o>>=1) w += __shfl_down_sync(0xffffffffu, w, o);
    if (!lane) sm[0] = w;
  }
  __syncthreads();
  float r = sm[0];
  __syncthreads();
  return r;
}

// ----------------------------- concat + router -----------------------------
__global__ __launch_bounds__(256) void concat_router_kernel(
    const float* __restrict__ pose, const float* __restrict__ scene,
    const float* __restrict__ f1w, const float* __restrict__ f1b,
    const float* __restrict__ f2w, const float* __restrict__ f2b,
    float* __restrict__ X, float* __restrict__ R)
{
  int t = blockIdx.x;
  int b = t >> 9, s = t & 511;
  const float* src = (s < 256) ? pose + (size_t)((b<<8)+s)*HD
                               : scene + (size_t)((b<<8)+(s-256))*HD;
  const float4* s4 = (const float4*)src;
  float4* d4 = (float4*)(X + (size_t)t*HD);
  float4 v = s4[threadIdx.x];
  d4[threadIdx.x] = v;
  float vals[4] = {v.x, v.y, v.z, v.w};
  float acc[4] = {0.f,0.f,0.f,0.f};
  int i0 = threadIdx.x * 4;
  #pragma unroll
  for (int c=0;c<4;c++){
    #pragma unroll
    for (int e=0;e<4;e++) acc[e] += vals[c] * f1w[(i0+c)*4 + e];
  }
  __shared__ float sm[8][4];
  int lane = threadIdx.x & 31, warp = threadIdx.x >> 5;
  #pragma unroll
  for (int e=0;e<4;e++){
    float a = acc[e];
    #pragma unroll
    for (int o=16;o;o>>=1) a += __shfl_down_sync(0xffffffffu, a, o);
    if (!lane) sm[warp][e] = a;
  }
  __syncthreads();
  if (threadIdx.x == 0){
    float g[4];
    #pragma unroll
    for (int e=0;e<4;e++){
      float su = f1b[e];
      #pragma unroll
      for (int w=0;w<8;w++) su += sm[w][e];
      g[e] = 0.5f * su * (1.f + erff(su * 0.70710678118654752f));
    }
    float rr[4]; float tot = 0.f;
    #pragma unroll
    for (int j=0;j<4;j++){
      float z = f2b[j];
      #pragma unroll
      for (int e=0;e<4;e++) z += g[e] * f2w[e*4 + j];
      float sg = 1.f / (1.f + expf(-z));
      rr[j] = sg; tot += sg;
    }
    tot = fmaxf(tot, 1e-8f);
    #pragma unroll
    for (int j=0;j<4;j++) R[t*4 + j] = rr[j] / tot;
  }
}

// ----------------------------- RMSNorm --------------------------------------
__global__ __launch_bounds__(256) void rms_kernel(
    const float* __restrict__ x, const float* __restrict__ w, float* __restrict__ o)
{
  __shared__ float sm[32];
  int row = blockIdx.x;
  const float* xr = x + (size_t)row*HD;
  float ss = 0.f;
  for (int i=threadIdx.x; i<HD; i+=256){ float v = xr[i]; ss += v*v; }
  float tot = blockReduceSum(ss, sm);
  float sc = rsqrtf(tot * (1.f/HD) + 1e-5f);
  float* orow = o + (size_t)row*HD;
  for (int i=threadIdx.x; i<HD; i+=256) orow[i] = xr[i] * sc * w[i];
}

// ----------------------------- GEMM (f32x2) ---------------------------------
#define BM 128
#define BN 128
#define BK 16

__global__ __launch_bounds__(256) void gemm_kernel(
    const float* __restrict__ A, const float* __restrict__ W,
    const float* __restrict__ bias, const float* __restrict__ add,
    float* __restrict__ C, int M, int N, int K)
{
  __shared__ float As[BK][BM];
  __shared__ float Ws[BK][BN];
  int tid = threadIdx.x;
  int m0 = blockIdx.y * BM, n0 = blockIdx.x * BN;
  int tm = (tid >> 4) << 3;
  int tn = (tid & 15) << 3;
  unsigned long long acc[8][4];
  #pragma unroll
  for (int i=0;i<8;i++){
    #pragma unroll
    for (int j=0;j<4;j++) acc[i][j] = 0ULL;
  }
  int T = K >> 4;
  int arow0 = tid >> 2,          ac0 = (tid & 3) << 2;
  int arow1 = (tid >> 2) + 64,   ac1 = ac0;
  int wrow0 = tid >> 5,          wc0 = (tid & 31) << 2;
  int wrow1 = (tid >> 5) + 8,    wc1 = wc0;

  float4 ra0, ra1, rw0, rw1;
  const float4 z4 = make_float4(0.f,0.f,0.f,0.f);
  {
    int g0 = m0 + arow0, g1 = m0 + arow1;
    ra0 = (g0 < M) ? *(const float4*)(A + (size_t)g0*K + ac0) : z4;
    ra1 = (g1 < M) ? *(const float4*)(A + (size_t)g1*K + ac1) : z4;
    rw0 = *(const float4*)(W + (size_t)wrow0*N + n0 + wc0);
    rw1 = *(const float4*)(W + (size_t)wrow1*N + n0 + wc1);
  }
  for (int t=0; t<T; ++t){
    As[ac0+0][arow0]=ra0.x; As[ac0+1][arow0]=ra0.y; As[ac0+2][arow0]=ra0.z; As[ac0+3][arow0]=ra0.w;
    As[ac1+0][arow1]=ra1.x; As[ac1+1][arow1]=ra1.y; As[ac1+2][arow1]=ra1.z; As[ac1+3][arow1]=ra1.w;
    *(float4*)&Ws[wrow0][wc0] = rw0;
    *(float4*)&Ws[wrow1][wc1] = rw1;
    __syncthreads();
    if (t+1 < T){
      int kb = (t+1) << 4;
      int g0 = m0 + arow0, g1 = m0 + arow1;
      ra0 = (g0 < M) ? *(const float4*)(A + (size_t)g0*K + kb + ac0) : z4;
      ra1 = (g1 < M) ? *(const float4*)(A + (size_t)g1*K + kb + ac1) : z4;
      rw0 = *(const float4*)(W + (size_t)(kb+wrow0)*N + n0 + wc0);
      rw1 = *(const float4*)(W + (size_t)(kb+wrow1)*N + n0 + wc1);
    }
    #pragma unroll
    for (int kk=0; kk<BK; ++kk){
      float4 a0 = *(const float4*)&As[kk][tm];
      float4 a1 = *(const float4*)&As[kk][tm+4];
      const unsigned long long* wp = (const unsigned long long*)&Ws[kk][tn];
      unsigned long long b0 = wp[0], b1 = wp[1], b2 = wp[2], b3 = wp[3];
      unsigned long long p;
      #define ROWF(i, av) { p = pk2(av); ffma2(acc[i][0],p,b0); ffma2(acc[i][1],p,b1); \
                            ffma2(acc[i][2],p,b2); ffma2(acc[i][3],p,b3); }
      ROWF(0, a0.x) ROWF(1, a0.y) ROWF(2, a0.z) ROWF(3, a0.w)
      ROWF(4, a1.x) ROWF(5, a1.y) ROWF(6, a1.z) ROWF(7, a1.w)
      #undef ROWF
    }
    __syncthreads();
  }
  #pragma unroll
  for (int i=0;i<8;i++){
    int row = m0 + tm + i;
    if (row >= M) continue;
    size_t rb = (size_t)row * N;
    #pragma unroll
    for (int j=0;j<4;j++){
      F2U v; v.u = acc[i][j];
      int col = n0 + tn + j*2;
      float e0 = v.f.x, e1 = v.f.y;
      if (bias){ e0 += bias[col]; e1 += bias[col+1]; }
      if (add){ e0 += add[rb+col]; e1 += add[rb+col+1]; }
      C[rb+col] = e0; C[rb+col+1] = e1;
    }
  }
}

// ----------------------------- attention ------------------------------------
#define QS 65
#define ATTN_SMEM ((32*QS + 64*QS + 32*512) * 4)

__global__ __launch_bounds__(256) void attn_kernel(
    const float* __restrict__ Q, const float* __restrict__ K,
    const float* __restrict__ V, float* __restrict__ O, int q_per_b)
{
  extern __shared__ float smem[];
  float* Qs = smem;              // 32*QS
  float* KV = Qs + 32*QS;        // 64*QS
  float* S  = KV + 64*QS;        // 32*512
  int tid = threadIdx.x;
  int bh = blockIdx.y; int b = bh >> 4, h = bh & 15;
  int q0 = blockIdx.x * 32;
  // load Q tile (invalid rows -> 0)
  #pragma unroll
  for (int i=0;i<8;i++){
    int idx = tid + i*256; int qi = idx >> 6, d = idx & 63;
    float v = 0.f;
    if (q0 + qi < q_per_b) v = Q[(size_t)(b*q_per_b + q0 + qi)*HD + h*64 + d];
    Qs[qi*QS + d] = v;
  }
  __syncthreads();
  int sgrp = tid & 15, qgrp = tid >> 4;
  // pass 1: scores
  for (int kt=0; kt<8; ++kt){
    #pragma unroll
    for (int i=0;i<16;i++){
      int idx = tid + i*256; int sk = idx >> 6, d = idx & 63;
      KV[sk*QS + d] = K[(size_t)(b*512 + kt*64 + sk)*HD + h*64 + d];
    }
    __syncthreads();
    float a00=0,a01=0,a02=0,a03=0,a10=0,a11=0,a12=0,a13=0;
    #pragma unroll 8
    for (int d=0; d<64; ++d){
      float q0v = Qs[(qgrp*2  )*QS + d];
      float q1v = Qs[(qgrp*2+1)*QS + d];
      float k0 = KV[(sgrp*4  )*QS + d];
      float k1 = KV[(sgrp*4+1)*QS + d];
      float k2 = KV[(sgrp*4+2)*QS + d];
      float k3 = KV[(sgrp*4+3)*QS + d];
      a00 += q0v*k0; a01 += q0v*k1; a02 += q0v*k2; a03 += q0v*k3;
      a10 += q1v*k0; a11 += q1v*k1; a12 += q1v*k2; a13 += q1v*k3;
    }
    int r0 = (qgrp*2)*512 + kt*64 + sgrp*4, r1 = r0 + 512;
    S[r0+0]=a00*0.125f; S[r0+1]=a01*0.125f; S[r0+2]=a02*0.125f; S[r0+3]=a03*0.125f;
    S[r1+0]=a10*0.125f; S[r1+1]=a11*0.125f; S[r1+2]=a12*0.125f; S[r1+3]=a13*0.125f;
    __syncthreads();
  }
  // softmax (each warp: 4 rows)
  int lane = tid & 31, warp = tid >> 5;
  for (int rr=0; rr<4; ++rr){
    int qi = warp*4 + rr;
    float m = -1e30f;
    for (int j=lane; j<512; j+=32) m = fmaxf(m, S[qi*512 + j]);
    #pragma unroll
    for (int o=16;o;o>>=1) m = fmaxf(m, __shfl_xor_sync(0xffffffffu, m, o));
    float ssum = 0.f;
    for (int j=lane; j<512; j+=32){ float e = __expf(S[qi*512+j] - m); S[qi*512+j] = e; ssum += e; }
    #pragma unroll
    for (int o=16;o;o>>=1) ssum += __shfl_xor_sync(0xffffffffu, ssum, o);
    float inv = 1.f / ssum;
    for (int j=lane; j<512; j+=32) S[qi*512+j] *= inv;
  }
  __syncthreads();
  // pass 2: O = P @ V
  int dgrp = sgrp;
  float o00=0,o01=0,o02=0,o03=0,o10=0,o11=0,o12=0,o13=0;
  for (int kt=0; kt<8; ++kt){
    #pragma unroll
    for (int i=0;i<16;i++){
      int idx = tid + i*256; int sk = idx >> 6, d = idx & 63;
      KV[sk*QS + d] = V[(size_t)(b*512 + kt*64 + sk)*HD + h*64 + d];
    }
    __syncthreads();
    #pragma unroll 4
    for (int sk=0; sk<64; ++sk){
      float p0 = S[(qgrp*2  )*512 + kt*64 + sk];
      float p1 = S[(qgrp*2+1)*512 + kt*64 + sk];
      float v0 = KV[sk*QS + dgrp*4+0];
      float v1 = KV[sk*QS + dgrp*4+1];
      float v2 = KV[sk*QS + dgrp*4+2];
      float v3 = KV[sk*QS + dgrp*4+3];
      o00 += p0*v0; o01 += p0*v1; o02 += p0*v2; o03 += p0*v3;
      o10 += p1*v0; o11 += p1*v1; o12 += p1*v2; o13 += p1*v3;
    }
    __syncthreads();
  }
  {
    int qi = qgrp*2;
    if (q0 + qi < q_per_b){
      size_t base = (size_t)(b*q_per_b + q0 + qi)*HD + h*64 + dgrp*4;
      O[base+0]=o00; O[base+1]=o01; O[base+2]=o02; O[base+3]=o03;
    }
    qi = qgrp*2 + 1;
    if (q0 + qi < q_per_b){
      size_t base = (size_t)(b*q_per_b + q0 + qi)*HD + h*64 + dgrp*4;
      O[base+0]=o10; O[base+1]=o11; O[base+2]=o12; O[base+3]=o13;
    }
  }
}

// ----------------------------- small kernels --------------------------------
__global__ __launch_bounds__(256) void silu_mul_kernel(float* __restrict__ u,
                                                       const float* __restrict__ t, int n)
{
  int i = blockIdx.x * 256 + threadIdx.x;
  if (i < n){ float x = u[i]; u[i] = (x / (1.f + __expf(-x))) * t[i]; }
}

__global__ __launch_bounds__(256) void gather240_kernel(const float* __restrict__ in,
                                                        float* __restrict__ out)
{
  int j = blockIdx.x;
  int gr = (j/30)*512 + (j%30);
  const float4* s = (const float4*)(in + (size_t)gr*HD);
  float4* d = (float4*)(out + (size_t)j*HD);
  d[threadIdx.x] = s[threadIdx.x];
}

__global__ __launch_bounds__(256) void combine240_kernel(const float* __restrict__ h,
    const float* __restrict__ r, int e, int first, float* __restrict__ C)
{
  int j = blockIdx.x;
  int gr = (j/30)*512 + (j%30);
  float w = r[gr*4 + e];
  for (int c=threadIdx.x; c<HD; c+=256){
    float v = h[(size_t)j*HD + c] * w;
    C[(size_t)j*HD + c] = first ? v : C[(size_t)j*HD + c] + v;
  }
}

__global__ __launch_bounds__(256) void layernorm_kernel(const float* __restrict__ y,
    const float* __restrict__ w, const float* __restrict__ bb, float* __restrict__ out)
{
  __shared__ float sm[32];
  int row = blockIdx.x;
  const float* yr = y + (size_t)row*HD;
  float s = 0.f, sq = 0.f;
  for (int i=threadIdx.x; i<HD; i+=256){ float v = yr[i]; s += v; sq += v*v; }
  float ts = blockReduceSum(s, sm);
  float tq = blockReduceSum(sq, sm);
  float mu = ts * (1.f/HD);
  float var = tq * (1.f/HD) - mu*mu;
  float inv = rsqrtf(var + 1e-5f);
  float* orow = out + (size_t)row*HD;
  for (int i=threadIdx.x; i<HD; i+=256) orow[i] = (yr[i] - mu) * inv * w[i] + bb[i];
}

// ----------------------------- host orchestration ---------------------------
extern "C" void kernel_launch(void* const* d_in, const int* in_sizes, int n_in,
                              void* d_out, int out_size)
{
  const float* pose = (const float*)d_in[0];
  const float* scene= (const float*)d_in[1];
  const float* rf1w = (const float*)d_in[2];
  const float* rf1b = (const float*)d_in[3];
  const float* rf2w = (const float*)d_in[4];
  const float* rf2b = (const float*)d_in[5];
  const float* anw  = (const float*)d_in[6];
  const float* wq   = (const float*)d_in[7];
  const float* wqb  = (const float*)d_in[8];
  const float* wk   = (const float*)d_in[9];
  const float* wkb  = (const float*)d_in[10];
  const float* wv   = (const float*)d_in[11];
  const float* wvb  = (const float*)d_in[12];
  const float* wo   = (const float*)d_in[13];
  const float* wob  = (const float*)d_in[14];
  const float* fnw  = (const float*)d_in[15];
  const float* w1   = (const float*)d_in[16];
  const float* w2   = (const float*)d_in[17];
  const float* w3   = (const float*)d_in[18];
  const float* pw   = (const float*)d_in[19];
  const float* pb   = (const float*)d_in[20];
  const float* lnw  = (const float*)d_in[21];
  const float* lnb  = (const float*)d_in[22];

  float *X,*R,*H,*H2,*XN,*Q,*K,*V,*O,*U,*T;
  float *cXN,*cH,*cQ,*cO,*cH2,*cU,*cT,*cF,*C,*Y;
  cudaGetSymbolAddress((void**)&X,  g_X);
  cudaGetSymbolAddress((void**)&R,  g_R);
  cudaGetSymbolAddress((void**)&H,  g_H);
  cudaGetSymbolAddress((void**)&H2, g_H2);
  cudaGetSymbolAddress((void**)&XN, g_XN);
  cudaGetSymbolAddress((void**)&Q,  g_Q);
  cudaGetSymbolAddress((void**)&K,  g_K);
  cudaGetSymbolAddress((void**)&V,  g_V);
  cudaGetSymbolAddress((void**)&O,  g_O);
  cudaGetSymbolAddress((void**)&U,  g_U);
  cudaGetSymbolAddress((void**)&T,  g_T);
  cudaGetSymbolAddress((void**)&cXN,g_cXN);
  cudaGetSymbolAddress((void**)&cH, g_cH);
  cudaGetSymbolAddress((void**)&cQ, g_cQ);
  cudaGetSymbolAddress((void**)&cO, g_cO);
  cudaGetSymbolAddress((void**)&cH2,g_cH2);
  cudaGetSymbolAddress((void**)&cU, g_cU);
  cudaGetSymbolAddress((void**)&cT, g_cT);
  cudaGetSymbolAddress((void**)&cF, g_cF);
  cudaGetSymbolAddress((void**)&C,  g_C);
  cudaGetSymbolAddress((void**)&Y,  g_Y);

  cudaFuncSetAttribute(attn_kernel, cudaFuncAttributeMaxDynamicSharedMemorySize, ATTN_SMEM);

  concat_router_kernel<<<NTOK, 256>>>(pose, scene, rf1w, rf1b, rf2w, rf2b, X, R);

  const size_t HH = (size_t)HD*HD;
  const size_t HHF = (size_t)HD*HF;
  dim3 gFull1024(8, 32);    // M=4096 N=1024
  dim3 gFullHF(22, 32);     // M=4096 N=2816
  dim3 gCmp1024(8, 2);      // M=240  N=1024
  dim3 gCmpHF(22, 2);       // M=240  N=2816

  for (int e=0; e<4; ++e){
    cudaMemcpyAsync(H, X, (size_t)NTOK*HD*sizeof(float), cudaMemcpyDeviceToDevice, 0);

    // ---- layer 0 (full) ----
    int el = e*2 + 0;
    rms_kernel<<<NTOK, 256>>>(H, anw + (size_t)el*HD, XN);
    gemm_kernel<<<gFull1024, 256>>>(XN, wq + el*HH, wqb + (size_t)el*HD, nullptr, Q, NTOK, HD, HD);
    gemm_kernel<<<gFull1024, 256>>>(XN, wk + el*HH, wkb + (size_t)el*HD, nullptr, K, NTOK, HD, HD);
    gemm_kernel<<<gFull1024, 256>>>(XN, wv + el*HH, wvb + (size_t)el*HD, nullptr, V, NTOK, HD, HD);
    attn_kernel<<<dim3(16,128), 256, ATTN_SMEM>>>(Q, K, V, O, 512);
    gemm_kernel<<<gFull1024, 256>>>(O, wo + el*HH, wob + (size_t)el*HD, H, H2, NTOK, HD, HD);
    rms_kernel<<<NTOK, 256>>>(H2, fnw + (size_t)el*HD, XN);
    gemm_kernel<<<gFullHF, 256>>>(XN, w1 + el*HHF, nullptr, nullptr, U, NTOK, HF, HD);
    gemm_kernel<<<gFullHF, 256>>>(XN, w3 + el*HHF, nullptr, nullptr, T, NTOK, HF, HD);
    silu_mul_kernel<<<(NTOK*HF + 255)/256, 256>>>(U, T, NTOK*HF);
    gemm_kernel<<<gFull1024, 256>>>(U, w2 + el*HHF, nullptr, H2, H, NTOK, HD, HF);

    // ---- layer 1 (K/V full, rest compact 240 rows) ----
    el = e*2 + 1;
    rms_kernel<<<NTOK, 256>>>(H, anw + (size_t)el*HD, XN);
    gemm_kernel<<<gFull1024, 256>>>(XN, wk + el*HH, wkb + (size_t)el*HD, nullptr, K, NTOK, HD, HD);
    gemm_kernel<<<gFull1024, 256>>>(XN, wv + el*HH, wvb + (size_t)el*HD, nullptr, V, NTOK, HD, HD);
    gather240_kernel<<<NKEEP, 256>>>(XN, cXN);
    gather240_kernel<<<NKEEP, 256>>>(H, cH);
    gemm_kernel<<<gCmp1024, 256>>>(cXN, wq + el*HH, wqb + (size_t)el*HD, nullptr, cQ, NKEEP, HD, HD);
    attn_kernel<<<dim3(1,128), 256, ATTN_SMEM>>>(cQ, K, V, cO, 30);
    gemm_kernel<<<gCmp1024, 256>>>(cO, wo + el*HH, wob + (size_t)el*HD, cH, cH2, NKEEP, HD, HD);
    rms_kernel<<<NKEEP, 256>>>(cH2, fnw + (size_t)el*HD, cXN);
    gemm_kernel<<<gCmpHF, 256>>>(cXN, w1 + el*HHF, nullptr, nullptr, cU, NKEEP, HF, HD);
    gemm_kernel<<<gCmpHF, 256>>>(cXN, w3 + el*HHF, nullptr, nullptr, cT, NKEEP, HF, HD);
    silu_mul_kernel<<<(NKEEP*HF + 255)/256, 256>>>(cU, cT, NKEEP*HF);
    gemm_kernel<<<gCmp1024, 256>>>(cU, w2 + el*HHF, nullptr, cH2, cF, NKEEP, HD, HF);
    combine240_kernel<<<NKEEP, 256>>>(cF, R, e, (e==0) ? 1 : 0, C);
  }

  // ---- final projection + LayerNorm ----
  gemm_kernel<<<gCmp1024, 256>>>(C, pw, pb, nullptr, Y, NKEEP, HD, HD);
  layernorm_kernel<<<NKEEP, 256>>>(Y, lnw, lnb, (float*)d_out);
}

// round 15
// speedup vs baseline: 1.7023x; 1.7023x over previous
#include <cuda_runtime.h>
#include <cuda_bf16.h>
#include <math.h>
#include <stdint.h>

// ---------------------------------------------------------------------------
// HawkeyeMoE: H=1024, E=4, L=2, NH=16, DH=64, B=8, S=512, HF=2816, KEEP=30
// Big GEMMs: mma.sync bf16 hi/lo split (3-pass, fp32-accurate), cp.async pipe.
// Compact GEMMs (M=240): fp32 FFMA2.
// ---------------------------------------------------------------------------
#define NTOK 4096
#define HD   1024
#define HF   2816
#define NKEEP 240

// ----------------------------- fp32 scratch ---------------------------------
__device__ float g_X [NTOK*HD];
__device__ float g_R [NTOK*4];
__device__ float g_H [NTOK*HD];
__device__ float g_H2[NTOK*HD];
__device__ float g_XN[NTOK*HD];
__device__ float g_Q [NTOK*HD];
__device__ float g_K [NTOK*HD];
__device__ float g_V [NTOK*HD];
__device__ float g_O [NTOK*HD];
__device__ float g_U [NTOK*HF];
__device__ float g_T [NTOK*HF];
__device__ float g_cXN[NKEEP*HD];
__device__ float g_cH [NKEEP*HD];
__device__ float g_cQ [NKEEP*HD];
__device__ float g_cO [NKEEP*HD];
__device__ float g_cH2[NKEEP*HD];
__device__ float g_cU [NKEEP*HF];
__device__ float g_cT [NKEEP*HF];
__device__ float g_cF [NKEEP*HD];
__device__ float g_C  [NKEEP*HD];
__device__ float g_Y  [NKEEP*HD];

// ----------------------------- bf16 hi/lo buffers ---------------------------
#define WQN (8*1024*1024)
#define WFN (8*1024*2816)
__device__ __nv_bfloat16 g_wq_h[WQN], g_wq_l[WQN];
__device__ __nv_bfloat16 g_wk_h[WQN], g_wk_l[WQN];
__device__ __nv_bfloat16 g_wv_h[WQN], g_wv_l[WQN];
__device__ __nv_bfloat16 g_wo_h[WQN], g_wo_l[WQN];
__device__ __nv_bfloat16 g_w1_h[WFN], g_w1_l[WFN];
__device__ __nv_bfloat16 g_w2_h[WFN], g_w2_l[WFN];
__device__ __nv_bfloat16 g_w3_h[WFN], g_w3_l[WFN];
__device__ __nv_bfloat16 g_Ahb[NTOK*HF], g_Alb[NTOK*HF];

// ----------------------------- helpers -------------------------------------
union F2U { float2 f; unsigned long long u; };

__device__ __forceinline__ unsigned long long pk2(float x){
  F2U c; c.f = make_float2(x, x); return c.u;
}
__device__ __forceinline__ void ffma2(unsigned long long &c, unsigned long long a, unsigned long long b){
  asm("fma.rn.f32x2 %0, %1, %2, %0;" : "+l"(c) : "l"(a), "l"(b));
}

__device__ __forceinline__ float blockReduceSum(float v, float* sm){
  int lane = threadIdx.x & 31, warp = threadIdx.x >> 5;
  #pragma unroll
  for (int o=16;o;o>>=1) v += __shfl_down_sync(0xffffffffu, v, o);
  if (!lane) sm[warp] = v;
  __syncthreads();
  if (warp == 0){
    float w = (lane < (int)(blockDim.x >> 5)) ? sm[lane] : 0.f;
    #pragma unroll
    for (int o=16;o;o>>=1) w += __shfl_down_sync(0xffffffffu, w, o);
    if (!lane) sm[0] = w;
  }
  __syncthreads();
  float r = sm[0];
  __syncthreads();
  return r;
}

__device__ __forceinline__ uint32_t smem_u32(const void* p) {
  uint32_t a;
  asm("{ .reg .u64 t; cvta.to.shared.u64 t, %1; cvt.u32.u64 %0, t; }"
      : "=r"(a) : "l"(p));
  return a;
}

// ------------------------- mma.sync building blocks --------------------------
__device__ __forceinline__ void cpa16(uint32_t d, const void* s){
  asm volatile("cp.async.cg.shared.global [%0], [%1], 16;" :: "r"(d), "l"(s));
}
#define CP_COMMIT asm volatile("cp.async.commit_group;" ::: "memory")
#define CP_WAIT1  asm volatile("cp.async.wait_group 1;" ::: "memory")
#define CP_WAIT0  asm volatile("cp.async.wait_group 0;" ::: "memory")

#define LDM_X4(r0,r1,r2,r3,a) \
  asm volatile("ldmatrix.sync.aligned.m8n8.x4.shared.b16 {%0,%1,%2,%3}, [%4];" \
    : "=r"(r0),"=r"(r1),"=r"(r2),"=r"(r3) : "r"(a))
#define LDM_X4T(r0,r1,r2,r3,a) \
  asm volatile("ldmatrix.sync.aligned.m8n8.x4.trans.shared.b16 {%0,%1,%2,%3}, [%4];" \
    : "=r"(r0),"=r"(r1),"=r"(r2),"=r"(r3) : "r"(a))

#define MMA16816(c, a, b) \
  asm volatile("mma.sync.aligned.m16n8k16.row.col.f32.bf16.bf16.f32 " \
    "{%0,%1,%2,%3}, {%4,%5,%6,%7}, {%8,%9}, {%0,%1,%2,%3};" \
    : "+f"((c)[0]),"+f"((c)[1]),"+f"((c)[2]),"+f"((c)[3]) \
    : "r"((a)[0]),"r"((a)[1]),"r"((a)[2]),"r"((a)[3]), "r"((b)[0]),"r"((b)[1]))

// ---------------------- fp32 -> bf16 hi/lo conversion ------------------------
__global__ __launch_bounds__(256) void cvt_kernel(const float* __restrict__ in,
    __nv_bfloat16* __restrict__ h, __nv_bfloat16* __restrict__ l, int n4)
{
  int i = blockIdx.x*256 + threadIdx.x;
  if (i >= n4) return;
  float4 v = ((const float4*)in)[i];
  __nv_bfloat16 h0=__float2bfloat16(v.x), h1=__float2bfloat16(v.y);
  __nv_bfloat16 h2=__float2bfloat16(v.z), h3=__float2bfloat16(v.w);
  __nv_bfloat16 l0=__float2bfloat16(v.x-__bfloat162float(h0));
  __nv_bfloat16 l1=__float2bfloat16(v.y-__bfloat162float(h1));
  __nv_bfloat16 l2=__float2bfloat16(v.z-__bfloat162float(h2));
  __nv_bfloat16 l3=__float2bfloat16(v.w-__bfloat162float(h3));
  uint2 hp, lp;
  hp.x = ((uint32_t)__bfloat16_as_ushort(h1)<<16) | __bfloat16_as_ushort(h0);
  hp.y = ((uint32_t)__bfloat16_as_ushort(h3)<<16) | __bfloat16_as_ushort(h2);
  lp.x = ((uint32_t)__bfloat16_as_ushort(l1)<<16) | __bfloat16_as_ushort(l0);
  lp.y = ((uint32_t)__bfloat16_as_ushort(l3)<<16) | __bfloat16_as_ushort(l2);
  ((uint2*)h)[i] = hp;
  ((uint2*)l)[i] = lp;
}

// ---------------------- tensor GEMM: C = A @ W (+bias)(+add) -----------------
// A hi/lo [M,K] bf16 row-major, W hi/lo [K,N] bf16 row-major.
// M,N multiples of 128; K multiple of 16.
#define NSTG   3
#define APITCH 48
#define ABYTES (128*APITCH)        // 6144
#define BBYTES 4096                // 16 rows * 256B
#define STGB   (2*ABYTES + 2*BBYTES)   // 20480
#define TG2_SMEM (NSTG*STGB)       // 61440

__global__ __launch_bounds__(256,1) void tgemm2_kernel(
    const __nv_bfloat16* __restrict__ Ah, const __nv_bfloat16* __restrict__ Al,
    const __nv_bfloat16* __restrict__ Bh, const __nv_bfloat16* __restrict__ Bl,
    const float* __restrict__ bias, const float* __restrict__ add,
    float* __restrict__ C, int M, int N, int K)
{
  extern __shared__ char smemraw[];
  uint32_t sb = smem_u32(smemraw);
  int tid = threadIdx.x, lane = tid & 31, wid = tid >> 5;
  int m0 = blockIdx.y << 7, n0 = blockIdx.x << 7;
  int warp_m = (wid >> 2) << 6, warp_n = (wid & 3) << 5;
  int T = K >> 4;

  // per-thread cp.async indices (1024 16B chunks/stage, 4 per thread)
  int am = tid >> 1, ac = tid & 1;
  const __nv_bfloat16* agh = Ah + (size_t)(m0+am)*K + ac*8;
  const __nv_bfloat16* agl = Al + (size_t)(m0+am)*K + ac*8;
  uint32_t adst = am*APITCH + ac*16;
  int bk = tid >> 4, bc = tid & 15;
  const __nv_bfloat16* bgh = Bh + (size_t)bk*N + n0 + bc*8;
  const __nv_bfloat16* bgl = Bl + (size_t)bk*N + n0 + bc*8;
  uint32_t bdst = bk*256 + ((uint32_t)(bc ^ (bk & 7)) << 4);

  #define LOAD_STAGE(t, s) do { \
    uint32_t so_ = sb + (uint32_t)(s)*STGB; \
    int k0e_ = (t) << 4; \
    cpa16(so_ + adst,                     agh + k0e_); \
    cpa16(so_ + ABYTES + adst,            agl + k0e_); \
    cpa16(so_ + 2*ABYTES + bdst,          bgh + (size_t)k0e_*N); \
    cpa16(so_ + 2*ABYTES + BBYTES + bdst, bgl + (size_t)k0e_*N); \
    CP_COMMIT; \
  } while(0)

  float acc[4][4][4];
  #pragma unroll
  for (int i=0;i<4;i++)
    #pragma unroll
    for (int j=0;j<4;j++)
      #pragma unroll
      for (int k=0;k<4;k++) acc[i][j][k] = 0.f;

  LOAD_STAGE(0, 0);
  LOAD_STAGE(1, 1);

  // fragment smem addresses
  int arow = warp_m + ((lane>>3)&1)*8 + (lane&7);
  uint32_t aoff = (uint32_t)arow*APITCH + (uint32_t)(lane>>4)*16;
  int kk = lane & 15;

  for (int t=0; t<T; ++t){
    if (t+1 < T) { CP_WAIT1; } else { CP_WAIT0; }
    __syncthreads();
    if (t+2 < T) LOAD_STAGE(t+2, (t+2)%NSTG);

    uint32_t so = sb + (uint32_t)(t%NSTG)*STGB;
    uint32_t ah[4][4], alr[4][4], bh[4][2], blr[4][2];
    #pragma unroll
    for (int mt=0; mt<4; ++mt){
      uint32_t a = so + aoff + (uint32_t)mt*16*APITCH;
      LDM_X4(ah[mt][0], ah[mt][1], ah[mt][2], ah[mt][3], a);
      LDM_X4(alr[mt][0], alr[mt][1], alr[mt][2], alr[mt][3], a + ABYTES);
    }
    #pragma unroll
    for (int np=0; np<2; ++np){
      uint32_t c = (uint32_t)(warp_n>>3) + np*2 + (lane>>4);
      uint32_t phys = c ^ (uint32_t)(kk & 7);
      uint32_t a = so + 2*ABYTES + (uint32_t)kk*256 + phys*16;
      uint32_t r0,r1,r2,r3;
      LDM_X4T(r0,r1,r2,r3, a);
      bh[np*2][0]=r0; bh[np*2][1]=r1; bh[np*2+1][0]=r2; bh[np*2+1][1]=r3;
      LDM_X4T(r0,r1,r2,r3, a + BBYTES);
      blr[np*2][0]=r0; blr[np*2][1]=r1; blr[np*2+1][0]=r2; blr[np*2+1][1]=r3;
    }
    // pass 1: hi*hi
    #pragma unroll
    for (int mt=0; mt<4; ++mt)
      #pragma unroll
      for (int nt=0; nt<4; ++nt) MMA16816(acc[mt][nt], ah[mt], bh[nt]);
    // pass 2: lo*hi
    #pragma unroll
    for (int mt=0; mt<4; ++mt)
      #pragma unroll
      for (int nt=0; nt<4; ++nt) MMA16816(acc[mt][nt], alr[mt], bh[nt]);
    // pass 3: hi*lo
    #pragma unroll
    for (int mt=0; mt<4; ++mt)
      #pragma unroll
      for (int nt=0; nt<4; ++nt) MMA16816(acc[mt][nt], ah[mt], blr[nt]);
  }
  #undef LOAD_STAGE

  // epilogue
  int g = lane >> 2, c2 = (lane & 3) << 1;
  #pragma unroll
  for (int mt=0; mt<4; ++mt){
    #pragma unroll
    for (int nt=0; nt<4; ++nt){
      int r = m0 + warp_m + mt*16 + g;
      int col = n0 + warp_n + nt*8 + c2;
      size_t o0 = (size_t)r*N + col, o1 = o0 + (size_t)8*N;
      float x0=acc[mt][nt][0], x1=acc[mt][nt][1], x2=acc[mt][nt][2], x3=acc[mt][nt][3];
      if (bias){ float b0=bias[col], b1=bias[col+1]; x0+=b0; x1+=b1; x2+=b0; x3+=b1; }
      if (add){ x0+=add[o0]; x1+=add[o0+1]; x2+=add[o1]; x3+=add[o1+1]; }
      float2 v0 = make_float2(x0,x1), v1 = make_float2(x2,x3);
      *(float2*)(C+o0) = v0;
      *(float2*)(C+o1) = v1;
    }
  }
}

// ----------------------------- concat + router -----------------------------
__global__ __launch_bounds__(256) void concat_router_kernel(
    const float* __restrict__ pose, const float* __restrict__ scene,
    const float* __restrict__ f1w, const float* __restrict__ f1b,
    const float* __restrict__ f2w, const float* __restrict__ f2b,
    float* __restrict__ X, float* __restrict__ R)
{
  int t = blockIdx.x;
  int b = t >> 9, s = t & 511;
  const float* src = (s < 256) ? pose + (size_t)((b<<8)+s)*HD
                               : scene + (size_t)((b<<8)+(s-256))*HD;
  const float4* s4 = (const float4*)src;
  float4* d4 = (float4*)(X + (size_t)t*HD);
  float4 v = s4[threadIdx.x];
  d4[threadIdx.x] = v;
  float vals[4] = {v.x, v.y, v.z, v.w};
  float acc[4] = {0.f,0.f,0.f,0.f};
  int i0 = threadIdx.x * 4;
  #pragma unroll
  for (int c=0;c<4;c++){
    #pragma unroll
    for (int e=0;e<4;e++) acc[e] += vals[c] * f1w[(i0+c)*4 + e];
  }
  __shared__ float sm[8][4];
  int lane = threadIdx.x & 31, warp = threadIdx.x >> 5;
  #pragma unroll
  for (int e=0;e<4;e++){
    float a = acc[e];
    #pragma unroll
    for (int o=16;o;o>>=1) a += __shfl_down_sync(0xffffffffu, a, o);
    if (!lane) sm[warp][e] = a;
  }
  __syncthreads();
  if (threadIdx.x == 0){
    float g[4];
    #pragma unroll
    for (int e=0;e<4;e++){
      float su = f1b[e];
      #pragma unroll
      for (int w=0;w<8;w++) su += sm[w][e];
      g[e] = 0.5f * su * (1.f + erff(su * 0.70710678118654752f));
    }
    float rr[4]; float tot = 0.f;
    #pragma unroll
    for (int j=0;j<4;j++){
      float z = f2b[j];
      #pragma unroll
      for (int e=0;e<4;e++) z += g[e] * f2w[e*4 + j];
      float sg = 1.f / (1.f + expf(-z));
      rr[j] = sg; tot += sg;
    }
    tot = fmaxf(tot, 1e-8f);
    #pragma unroll
    for (int j=0;j<4;j++) R[t*4 + j] = rr[j] / tot;
  }
}

// ----------------------------- RMSNorm --------------------------------------
__global__ __launch_bounds__(256) void rms_kernel(
    const float* __restrict__ x, const float* __restrict__ w, float* __restrict__ o)
{
  __shared__ float sm[32];
  int row = blockIdx.x;
  const float* xr = x + (size_t)row*HD;
  float ss = 0.f;
  for (int i=threadIdx.x; i<HD; i+=256){ float v = xr[i]; ss += v*v; }
  float tot = blockReduceSum(ss, sm);
  float sc = rsqrtf(tot * (1.f/HD) + 1e-5f);
  float* orow = o + (size_t)row*HD;
  for (int i=threadIdx.x; i<HD; i+=256) orow[i] = xr[i] * sc * w[i];
}

// ----------------------------- fp32 GEMM (compact M) ------------------------
#define BM 128
#define BN 128
#define BK 16

__global__ __launch_bounds__(256) void gemm_kernel(
    const float* __restrict__ A, const float* __restrict__ W,
    const float* __restrict__ bias, const float* __restrict__ add,
    float* __restrict__ C, int M, int N, int K)
{
  __shared__ float As[BK][BM];
  __shared__ float Ws[BK][BN];
  int tid = threadIdx.x;
  int m0 = blockIdx.y * BM, n0 = blockIdx.x * BN;
  int tm = (tid >> 4) << 3;
  int tn = (tid & 15) << 3;
  unsigned long long acc[8][4];
  #pragma unroll
  for (int i=0;i<8;i++){
    #pragma unroll
    for (int j=0;j<4;j++) acc[i][j] = 0ULL;
  }
  int T = K >> 4;
  int arow0 = tid >> 2,          ac0 = (tid & 3) << 2;
  int arow1 = (tid >> 2) + 64,   ac1 = ac0;
  int wrow0 = tid >> 5,          wc0 = (tid & 31) << 2;
  int wrow1 = (tid >> 5) + 8,    wc1 = wc0;

  float4 ra0, ra1, rw0, rw1;
  const float4 z4 = make_float4(0.f,0.f,0.f,0.f);
  {
    int g0 = m0 + arow0, g1 = m0 + arow1;
    ra0 = (g0 < M) ? *(const float4*)(A + (size_t)g0*K + ac0) : z4;
    ra1 = (g1 < M) ? *(const float4*)(A + (size_t)g1*K + ac1) : z4;
    rw0 = *(const float4*)(W + (size_t)wrow0*N + n0 + wc0);
    rw1 = *(const float4*)(W + (size_t)wrow1*N + n0 + wc1);
  }
  for (int t=0; t<T; ++t){
    As[ac0+0][arow0]=ra0.x; As[ac0+1][arow0]=ra0.y; As[ac0+2][arow0]=ra0.z; As[ac0+3][arow0]=ra0.w;
    As[ac1+0][arow1]=ra1.x; As[ac1+1][arow1]=ra1.y; As[ac1+2][arow1]=ra1.z; As[ac1+3][arow1]=ra1.w;
    *(float4*)&Ws[wrow0][wc0] = rw0;
    *(float4*)&Ws[wrow1][wc1] = rw1;
    __syncthreads();
    if (t+1 < T){
      int kb = (t+1) << 4;
      int g0 = m0 + arow0, g1 = m0 + arow1;
      ra0 = (g0 < M) ? *(const float4*)(A + (size_t)g0*K + kb + ac0) : z4;
      ra1 = (g1 < M) ? *(const float4*)(A + (size_t)g1*K + kb + ac1) : z4;
      rw0 = *(const float4*)(W + (size_t)(kb+wrow0)*N + n0 + wc0);
      rw1 = *(const float4*)(W + (size_t)(kb+wrow1)*N + n0 + wc1);
    }
    #pragma unroll
    for (int kk=0; kk<BK; ++kk){
      float4 a0 = *(const float4*)&As[kk][tm];
      float4 a1 = *(const float4*)&As[kk][tm+4];
      const unsigned long long* wp = (const unsigned long long*)&Ws[kk][tn];
      unsigned long long b0 = wp[0], b1 = wp[1], b2 = wp[2], b3 = wp[3];
      unsigned long long p;
      #define ROWF(i, av) { p = pk2(av); ffma2(acc[i][0],p,b0); ffma2(acc[i][1],p,b1); \
                            ffma2(acc[i][2],p,b2); ffma2(acc[i][3],p,b3); }
      ROWF(0, a0.x) ROWF(1, a0.y) ROWF(2, a0.z) ROWF(3, a0.w)
      ROWF(4, a1.x) ROWF(5, a1.y) ROWF(6, a1.z) ROWF(7, a1.w)
      #undef ROWF
    }
    __syncthreads();
  }
  #pragma unroll
  for (int i=0;i<8;i++){
    int row = m0 + tm + i;
    if (row >= M) continue;
    size_t rb = (size_t)row * N;
    #pragma unroll
    for (int j=0;j<4;j++){
      F2U v; v.u = acc[i][j];
      int col = n0 + tn + j*2;
      float e0 = v.f.x, e1 = v.f.y;
      if (bias){ e0 += bias[col]; e1 += bias[col+1]; }
      if (add){ e0 += add[rb+col]; e1 += add[rb+col+1]; }
      C[rb+col] = e0; C[rb+col+1] = e1;
    }
  }
}

// ----------------------------- attention ------------------------------------
#define QS 65
#define ATTN_SMEM ((32*QS + 64*QS + 32*512) * 4)

__global__ __launch_bounds__(256) void attn_kernel(
    const float* __restrict__ Q, const float* __restrict__ K,
    const float* __restrict__ V, float* __restrict__ O, int q_per_b)
{
  extern __shared__ float smem[];
  float* Qs = smem;              // 32*QS
  float* KV = Qs + 32*QS;        // 64*QS
  float* S  = KV + 64*QS;        // 32*512
  int tid = threadIdx.x;
  int bh = blockIdx.y; int b = bh >> 4, h = bh & 15;
  int q0 = blockIdx.x * 32;
  #pragma unroll
  for (int i=0;i<8;i++){
    int idx = tid + i*256; int qi = idx >> 6, d = idx & 63;
    float v = 0.f;
    if (q0 + qi < q_per_b) v = Q[(size_t)(b*q_per_b + q0 + qi)*HD + h*64 + d];
    Qs[qi*QS + d] = v;
  }
  __syncthreads();
  int sgrp = tid & 15, qgrp = tid >> 4;
  for (int kt=0; kt<8; ++kt){
    #pragma unroll
    for (int i=0;i<16;i++){
      int idx = tid + i*256; int sk = idx >> 6, d = idx & 63;
      KV[sk*QS + d] = K[(size_t)(b*512 + kt*64 + sk)*HD + h*64 + d];
    }
    __syncthreads();
    float a00=0,a01=0,a02=0,a03=0,a10=0,a11=0,a12=0,a13=0;
    #pragma unroll 8
    for (int d=0; d<64; ++d){
      float q0v = Qs[(qgrp*2  )*QS + d];
      float q1v = Qs[(qgrp*2+1)*QS + d];
      float k0 = KV[(sgrp*4  )*QS + d];
      float k1 = KV[(sgrp*4+1)*QS + d];
      float k2 = KV[(sgrp*4+2)*QS + d];
      float k3 = KV[(sgrp*4+3)*QS + d];
      a00 += q0v*k0; a01 += q0v*k1; a02 += q0v*k2; a03 += q0v*k3;
      a10 += q1v*k0; a11 += q1v*k1; a12 += q1v*k2; a13 += q1v*k3;
    }
    int r0 = (qgrp*2)*512 + kt*64 + sgrp*4, r1 = r0 + 512;
    S[r0+0]=a00*0.125f; S[r0+1]=a01*0.125f; S[r0+2]=a02*0.125f; S[r0+3]=a03*0.125f;
    S[r1+0]=a10*0.125f; S[r1+1]=a11*0.125f; S[r1+2]=a12*0.125f; S[r1+3]=a13*0.125f;
    __syncthreads();
  }
  int lane = tid & 31, warp = tid >> 5;
  for (int rr=0; rr<4; ++rr){
    int qi = warp*4 + rr;
    float m = -1e30f;
    for (int j=lane; j<512; j+=32) m = fmaxf(m, S[qi*512 + j]);
    #pragma unroll
    for (int o=16;o;o>>=1) m = fmaxf(m, __shfl_xor_sync(0xffffffffu, m, o));
    float ssum = 0.f;
    for (int j=lane; j<512; j+=32){ float e = __expf(S[qi*512+j] - m); S[qi*512+j] = e; ssum += e; }
    #pragma unroll
    for (int o=16;o;o>>=1) ssum += __shfl_xor_sync(0xffffffffu, ssum, o);
    float inv = 1.f / ssum;
    for (int j=lane; j<512; j+=32) S[qi*512+j] *= inv;
  }
  __syncthreads();
  int dgrp = sgrp;
  float o00=0,o01=0,o02=0,o03=0,o10=0,o11=0,o12=0,o13=0;
  for (int kt=0; kt<8; ++kt){
    #pragma unroll
    for (int i=0;i<16;i++){
      int idx = tid + i*256; int sk = idx >> 6, d = idx & 63;
      KV[sk*QS + d] = V[(size_t)(b*512 + kt*64 + sk)*HD + h*64 + d];
    }
    __syncthreads();
    #pragma unroll 4
    for (int sk=0; sk<64; ++sk){
      float p0 = S[(qgrp*2  )*512 + kt*64 + sk];
      float p1 = S[(qgrp*2+1)*512 + kt*64 + sk];
      float v0 = KV[sk*QS + dgrp*4+0];
      float v1 = KV[sk*QS + dgrp*4+1];
      float v2 = KV[sk*QS + dgrp*4+2];
      float v3 = KV[sk*QS + dgrp*4+3];
      o00 += p0*v0; o01 += p0*v1; o02 += p0*v2; o03 += p0*v3;
      o10 += p1*v0; o11 += p1*v1; o12 += p1*v2; o13 += p1*v3;
    }
    __syncthreads();
  }
  {
    int qi = qgrp*2;
    if (q0 + qi < q_per_b){
      size_t base = (size_t)(b*q_per_b + q0 + qi)*HD + h*64 + dgrp*4;
      O[base+0]=o00; O[base+1]=o01; O[base+2]=o02; O[base+3]=o03;
    }
    qi = qgrp*2 + 1;
    if (q0 + qi < q_per_b){
      size_t base = (size_t)(b*q_per_b + q0 + qi)*HD + h*64 + dgrp*4;
      O[base+0]=o10; O[base+1]=o11; O[base+2]=o12; O[base+3]=o13;
    }
  }
}

// ----------------------------- small kernels --------------------------------
__global__ __launch_bounds__(256) void silu_mul_kernel(float* __restrict__ u,
                                                       const float* __restrict__ t, int n)
{
  int i = blockIdx.x * 256 + threadIdx.x;
  if (i < n){ float x = u[i]; u[i] = (x / (1.f + __expf(-x))) * t[i]; }
}

__global__ __launch_bounds__(256) void gather240_kernel(const float* __restrict__ in,
                                                        float* __restrict__ out)
{
  int j = blockIdx.x;
  int gr = (j/30)*512 + (j%30);
  const float4* s = (const float4*)(in + (size_t)gr*HD);
  float4* d = (float4*)(out + (size_t)j*HD);
  d[threadIdx.x] = s[threadIdx.x];
}

__global__ __launch_bounds__(256) void combine240_kernel(const float* __restrict__ h,
    const float* __restrict__ r, int e, int first, float* __restrict__ C)
{
  int j = blockIdx.x;
  int gr = (j/30)*512 + (j%30);
  float w = r[gr*4 + e];
  for (int c=threadIdx.x; c<HD; c+=256){
    float v = h[(size_t)j*HD + c] * w;
    C[(size_t)j*HD + c] = first ? v : C[(size_t)j*HD + c] + v;
  }
}

__global__ __launch_bounds__(256) void layernorm_kernel(const float* __restrict__ y,
    const float* __restrict__ w, const float* __restrict__ bb, float* __restrict__ out)
{
  __shared__ float sm[32];
  int row = blockIdx.x;
  const float* yr = y + (size_t)row*HD;
  float s = 0.f, sq = 0.f;
  for (int i=threadIdx.x; i<HD; i+=256){ float v = yr[i]; s += v; sq += v*v; }
  float ts = blockReduceSum(s, sm);
  float tq = blockReduceSum(sq, sm);
  float mu = ts * (1.f/HD);
  float var = tq * (1.f/HD) - mu*mu;
  float inv = rsqrtf(var + 1e-5f);
  float* orow = out + (size_t)row*HD;
  for (int i=threadIdx.x; i<HD; i+=256) orow[i] = (yr[i] - mu) * inv * w[i] + bb[i];
}

// ----------------------------- host orchestration ---------------------------
extern "C" void kernel_launch(void* const* d_in, const int* in_sizes, int n_in,
                              void* d_out, int out_size)
{
  const float* pose = (const float*)d_in[0];
  const float* scene= (const float*)d_in[1];
  const float* rf1w = (const float*)d_in[2];
  const float* rf1b = (const float*)d_in[3];
  const float* rf2w = (const float*)d_in[4];
  const float* rf2b = (const float*)d_in[5];
  const float* anw  = (const float*)d_in[6];
  const float* wq   = (const float*)d_in[7];
  const float* wqb  = (const float*)d_in[8];
  const float* wk   = (const float*)d_in[9];
  const float* wkb  = (const float*)d_in[10];
  const float* wv   = (const float*)d_in[11];
  const float* wvb  = (const float*)d_in[12];
  const float* wo   = (const float*)d_in[13];
  const float* wob  = (const float*)d_in[14];
  const float* fnw  = (const float*)d_in[15];
  const float* w1   = (const float*)d_in[16];
  const float* w2   = (const float*)d_in[17];
  const float* w3   = (const float*)d_in[18];
  const float* pw   = (const float*)d_in[19];
  const float* pb   = (const float*)d_in[20];
  const float* lnw  = (const float*)d_in[21];
  const float* lnb  = (const float*)d_in[22];

  float *X,*R,*H,*H2,*XN,*Q,*K,*V,*O,*U,*T;
  float *cXN,*cH,*cQ,*cO,*cH2,*cU,*cT,*cF,*C,*Y;
  cudaGetSymbolAddress((void**)&X,  g_X);
  cudaGetSymbolAddress((void**)&R,  g_R);
  cudaGetSymbolAddress((void**)&H,  g_H);
  cudaGetSymbolAddress((void**)&H2, g_H2);
  cudaGetSymbolAddress((void**)&XN, g_XN);
  cudaGetSymbolAddress((void**)&Q,  g_Q);
  cudaGetSymbolAddress((void**)&K,  g_K);
  cudaGetSymbolAddress((void**)&V,  g_V);
  cudaGetSymbolAddress((void**)&O,  g_O);
  cudaGetSymbolAddress((void**)&U,  g_U);
  cudaGetSymbolAddress((void**)&T,  g_T);
  cudaGetSymbolAddress((void**)&cXN,g_cXN);
  cudaGetSymbolAddress((void**)&cH, g_cH);
  cudaGetSymbolAddress((void**)&cQ, g_cQ);
  cudaGetSymbolAddress((void**)&cO, g_cO);
  cudaGetSymbolAddress((void**)&cH2,g_cH2);
  cudaGetSymbolAddress((void**)&cU, g_cU);
  cudaGetSymbolAddress((void**)&cT, g_cT);
  cudaGetSymbolAddress((void**)&cF, g_cF);
  cudaGetSymbolAddress((void**)&C,  g_C);
  cudaGetSymbolAddress((void**)&Y,  g_Y);

  __nv_bfloat16 *wqh,*wql,*wkh,*wkl,*wvh,*wvl,*woh,*wol;
  __nv_bfloat16 *w1h,*w1l,*w2h,*w2l,*w3h,*w3l,*Abh,*Abl;
  cudaGetSymbolAddress((void**)&wqh, g_wq_h); cudaGetSymbolAddress((void**)&wql, g_wq_l);
  cudaGetSymbolAddress((void**)&wkh, g_wk_h); cudaGetSymbolAddress((void**)&wkl, g_wk_l);
  cudaGetSymbolAddress((void**)&wvh, g_wv_h); cudaGetSymbolAddress((void**)&wvl, g_wv_l);
  cudaGetSymbolAddress((void**)&woh, g_wo_h); cudaGetSymbolAddress((void**)&wol, g_wo_l);
  cudaGetSymbolAddress((void**)&w1h, g_w1_h); cudaGetSymbolAddress((void**)&w1l, g_w1_l);
  cudaGetSymbolAddress((void**)&w2h, g_w2_h); cudaGetSymbolAddress((void**)&w2l, g_w2_l);
  cudaGetSymbolAddress((void**)&w3h, g_w3_h); cudaGetSymbolAddress((void**)&w3l, g_w3_l);
  cudaGetSymbolAddress((void**)&Abh, g_Ahb);  cudaGetSymbolAddress((void**)&Abl, g_Alb);

  cudaFuncSetAttribute(attn_kernel, cudaFuncAttributeMaxDynamicSharedMemorySize, ATTN_SMEM);
  cudaFuncSetAttribute(tgemm2_kernel, cudaFuncAttributeMaxDynamicSharedMemorySize, TG2_SMEM);

  // ---- weight hi/lo conversion (once per launch) ----
  cvt_kernel<<<WQN/4/256, 256>>>(wq, wqh, wql, WQN/4);
  cvt_kernel<<<WQN/4/256, 256>>>(wk, wkh, wkl, WQN/4);
  cvt_kernel<<<WQN/4/256, 256>>>(wv, wvh, wvl, WQN/4);
  cvt_kernel<<<WQN/4/256, 256>>>(wo, woh, wol, WQN/4);
  cvt_kernel<<<WFN/4/256, 256>>>(w1, w1h, w1l, WFN/4);
  cvt_kernel<<<WFN/4/256, 256>>>(w2, w2h, w2l, WFN/4);
  cvt_kernel<<<WFN/4/256, 256>>>(w3, w3h, w3l, WFN/4);

  concat_router_kernel<<<NTOK, 256>>>(pose, scene, rf1w, rf1b, rf2w, rf2b, X, R);

  const size_t HH = (size_t)HD*HD;
  const size_t HHF = (size_t)HD*HF;
  dim3 tFull1024(HD/128, NTOK/128);   // (8, 32)
  dim3 tFullHF(HF/128, NTOK/128);     // (22, 32)
  dim3 gCmp1024(8, 2);                // M=240  N=1024
  dim3 gCmpHF(22, 2);                 // M=240  N=2816
  const int N4_H  = NTOK*HD/4;
  const int N4_HF = NTOK*HF/4;

  for (int e=0; e<4; ++e){
    cudaMemcpyAsync(H, X, (size_t)NTOK*HD*sizeof(float), cudaMemcpyDeviceToDevice, 0);

    // ---- layer 0 (full, tensor MMA) ----
    int el = e*2 + 0;
    rms_kernel<<<NTOK, 256>>>(H, anw + (size_t)el*HD, XN);
    cvt_kernel<<<N4_H/256, 256>>>(XN, Abh, Abl, N4_H);
    tgemm2_kernel<<<tFull1024, 256, TG2_SMEM>>>(Abh, Abl, wqh + el*HH, wql + el*HH, wqb + (size_t)el*HD, nullptr, Q, NTOK, HD, HD);
    tgemm2_kernel<<<tFull1024, 256, TG2_SMEM>>>(Abh, Abl, wkh + el*HH, wkl + el*HH, wkb + (size_t)el*HD, nullptr, K, NTOK, HD, HD);
    tgemm2_kernel<<<tFull1024, 256, TG2_SMEM>>>(Abh, Abl, wvh + el*HH, wvl + el*HH, wvb + (size_t)el*HD, nullptr, V, NTOK, HD, HD);
    attn_kernel<<<dim3(16,128), 256, ATTN_SMEM>>>(Q, K, V, O, 512);
    cvt_kernel<<<N4_H/256, 256>>>(O, Abh, Abl, N4_H);
    tgemm2_kernel<<<tFull1024, 256, TG2_SMEM>>>(Abh, Abl, woh + el*HH, wol + el*HH, wob + (size_t)el*HD, H, H2, NTOK, HD, HD);
    rms_kernel<<<NTOK, 256>>>(H2, fnw + (size_t)el*HD, XN);
    cvt_kernel<<<N4_H/256, 256>>>(XN, Abh, Abl, N4_H);
    tgemm2_kernel<<<tFullHF, 256, TG2_SMEM>>>(Abh, Abl, w1h + el*HHF, w1l + el*HHF, nullptr, nullptr, U, NTOK, HF, HD);
    tgemm2_kernel<<<tFullHF, 256, TG2_SMEM>>>(Abh, Abl, w3h + el*HHF, w3l + el*HHF, nullptr, nullptr, T, NTOK, HF, HD);
    silu_mul_kernel<<<(NTOK*HF + 255)/256, 256>>>(U, T, NTOK*HF);
    cvt_kernel<<<N4_HF/256, 256>>>(U, Abh, Abl, N4_HF);
    tgemm2_kernel<<<tFull1024, 256, TG2_SMEM>>>(Abh, Abl, w2h + el*HHF, w2l + el*HHF, nullptr, H2, H, NTOK, HD, HF);

    // ---- layer 1 (K/V full tensor, rest compact 240 rows fp32) ----
    el = e*2 + 1;
    rms_kernel<<<NTOK, 256>>>(H, anw + (size_t)el*HD, XN);
    cvt_kernel<<<N4_H/256, 256>>>(XN, Abh, Abl, N4_H);
    tgemm2_kernel<<<tFull1024, 256, TG2_SMEM>>>(Abh, Abl, wkh + el*HH, wkl + el*HH, wkb + (size_t)el*HD, nullptr, K, NTOK, HD, HD);
    tgemm2_kernel<<<tFull1024, 256, TG2_SMEM>>>(Abh, Abl, wvh + el*HH, wvl + el*HH, wvb + (size_t)el*HD, nullptr, V, NTOK, HD, HD);
    gather240_kernel<<<NKEEP, 256>>>(XN, cXN);
    gather240_kernel<<<NKEEP, 256>>>(H, cH);
    gemm_kernel<<<gCmp1024, 256>>>(cXN, wq + el*HH, wqb + (size_t)el*HD, nullptr, cQ, NKEEP, HD, HD);
    attn_kernel<<<dim3(1,128), 256, ATTN_SMEM>>>(cQ, K, V, cO, 30);
    gemm_kernel<<<gCmp1024, 256>>>(cO, wo + el*HH, wob + (size_t)el*HD, cH, cH2, NKEEP, HD, HD);
    rms_kernel<<<NKEEP, 256>>>(cH2, fnw + (size_t)el*HD, cXN);
    gemm_kernel<<<gCmpHF, 256>>>(cXN, w1 + el*HHF, nullptr, nullptr, cU, NKEEP, HF, HD);
    gemm_kernel<<<gCmpHF, 256>>>(cXN, w3 + el*HHF, nullptr, nullptr, cT, NKEEP, HF, HD);
    silu_mul_kernel<<<(NKEEP*HF + 255)/256, 256>>>(cU, cT, NKEEP*HF);
    gemm_kernel<<<gCmp1024, 256>>>(cU, w2 + el*HHF, nullptr, cH2, cF, NKEEP, HD, HF);
    combine240_kernel<<<NKEEP, 256>>>(cF, R, e, (e==0) ? 1 : 0, C);
  }

  // ---- final projection + LayerNorm ----
  gemm_kernel<<<gCmp1024, 256>>>(C, pw, pb, nullptr, Y, NKEEP, HD, HD);
  layernorm_kernel<<<NKEEP, 256>>>(Y, lnw, lnb, (float*)d_out);
}

// round 16
// speedup vs baseline: 1.7024x; 1.0000x over previous
#include <cuda_runtime.h>
#include <cuda_bf16.h>
#include <math.h>
#include <stdint.h>

// ---------------------------------------------------------------------------
// HawkeyeMoE: H=1024, E=4, L=2, NH=16, DH=64, B=8, S=512, HF=2816, KEEP=30
// Big GEMMs: mma.sync bf16 hi/lo split (3-pass, fp32-accurate), cp.async pipe.
// Compact GEMMs (M=240): fp32 FFMA2.
// ---------------------------------------------------------------------------
#define NTOK 4096
#define HD   1024
#define HF   2816
#define NKEEP 240

// ----------------------------- fp32 scratch ---------------------------------
__device__ float g_X [NTOK*HD];
__device__ float g_R [NTOK*4];
__device__ float g_H [NTOK*HD];
__device__ float g_H2[NTOK*HD];
__device__ float g_XN[NTOK*HD];
__device__ float g_Q [NTOK*HD];
__device__ float g_K [NTOK*HD];
__device__ float g_V [NTOK*HD];
__device__ float g_O [NTOK*HD];
__device__ float g_U [NTOK*HF];
__device__ float g_T [NTOK*HF];
__device__ float g_cXN[NKEEP*HD];
__device__ float g_cH [NKEEP*HD];
__device__ float g_cQ [NKEEP*HD];
__device__ float g_cO [NKEEP*HD];
__device__ float g_cH2[NKEEP*HD];
__device__ float g_cU [NKEEP*HF];
__device__ float g_cT [NKEEP*HF];
__device__ float g_cF [NKEEP*HD];
__device__ float g_C  [NKEEP*HD];
__device__ float g_Y  [NKEEP*HD];

// ----------------------------- bf16 hi/lo buffers ---------------------------
#define WQN (8*1024*1024)
#define WFN (8*1024*2816)
__device__ __nv_bfloat16 g_wq_h[WQN], g_wq_l[WQN];
__device__ __nv_bfloat16 g_wk_h[WQN], g_wk_l[WQN];
__device__ __nv_bfloat16 g_wv_h[WQN], g_wv_l[WQN];
__device__ __nv_bfloat16 g_wo_h[WQN], g_wo_l[WQN];
__device__ __nv_bfloat16 g_w1_h[WFN], g_w1_l[WFN];
__device__ __nv_bfloat16 g_w2_h[WFN], g_w2_l[WFN];
__device__ __nv_bfloat16 g_w3_h[WFN], g_w3_l[WFN];
__device__ __nv_bfloat16 g_Ahb[NTOK*HF], g_Alb[NTOK*HF];

// ----------------------------- helpers -------------------------------------
union F2U { float2 f; unsigned long long u; };

__device__ __forceinline__ unsigned long long pk2(float x){
  F2U c; c.f = make_float2(x, x); return c.u;
}
__device__ __forceinline__ void ffma2(unsigned long long &c, unsigned long long a, unsigned long long b){
  asm("fma.rn.f32x2 %0, %1, %2, %0;" : "+l"(c) : "l"(a), "l"(b));
}

__device__ __forceinline__ float blockReduceSum(float v, float* sm){
  int lane = threadIdx.x & 31, warp = threadIdx.x >> 5;
  #pragma unroll
  for (int o=16;o;o>>=1) v += __shfl_down_sync(0xffffffffu, v, o);
  if (!lane) sm[warp] = v;
  __syncthreads();
  if (warp == 0){
    float w = (lane < (int)(blockDim.x >> 5)) ? sm[lane] : 0.f;
    #pragma unroll
    for (int o=16;o;o>>=1) w += __shfl_down_sync(0xffffffffu, w, o);
    if (!lane) sm[0] = w;
  }
  __syncthreads();
  float r = sm[0];
  __syncthreads();
  return r;
}

__device__ __forceinline__ uint32_t smem_u32(const void* p) {
  uint32_t a;
  asm("{ .reg .u64 t; cvta.to.shared.u64 t, %1; cvt.u32.u64 %0, t; }"
      : "=r"(a) : "l"(p));
  return a;
}

// ------------------------- mma.sync building blocks --------------------------
__device__ __forceinline__ void cpa16(uint32_t d, const void* s){
  asm volatile("cp.async.cg.shared.global [%0], [%1], 16;" :: "r"(d), "l"(s));
}
#define CP_COMMIT asm volatile("cp.async.commit_group;" ::: "memory")
#define CP_WAIT1  asm volatile("cp.async.wait_group 1;" ::: "memory")
#define CP_WAIT0  asm volatile("cp.async.wait_group 0;" ::: "memory")

#define LDM_X4(r0,r1,r2,r3,a) \
  asm volatile("ldmatrix.sync.aligned.m8n8.x4.shared.b16 {%0,%1,%2,%3}, [%4];" \
    : "=r"(r0),"=r"(r1),"=r"(r2),"=r"(r3) : "r"(a))
#define LDM_X4T(r0,r1,r2,r3,a) \
  asm volatile("ldmatrix.sync.aligned.m8n8.x4.trans.shared.b16 {%0,%1,%2,%3}, [%4];" \
    : "=r"(r0),"=r"(r1),"=r"(r2),"=r"(r3) : "r"(a))

#define MMA16816(c, a, b) \
  asm volatile("mma.sync.aligned.m16n8k16.row.col.f32.bf16.bf16.f32 " \
    "{%0,%1,%2,%3}, {%4,%5,%6,%7}, {%8,%9}, {%0,%1,%2,%3};" \
    : "+f"((c)[0]),"+f"((c)[1]),"+f"((c)[2]),"+f"((c)[3]) \
    : "r"((a)[0]),"r"((a)[1]),"r"((a)[2]),"r"((a)[3]), "r"((b)[0]),"r"((b)[1]))

// ---------------------- fp32 -> bf16 hi/lo conversion ------------------------
__global__ __launch_bounds__(256) void cvt_kernel(const float* __restrict__ in,
    __nv_bfloat16* __restrict__ h, __nv_bfloat16* __restrict__ l, int n4)
{
  int i = blockIdx.x*256 + threadIdx.x;
  if (i >= n4) return;
  float4 v = ((const float4*)in)[i];
  __nv_bfloat16 h0=__float2bfloat16(v.x), h1=__float2bfloat16(v.y);
  __nv_bfloat16 h2=__float2bfloat16(v.z), h3=__float2bfloat16(v.w);
  __nv_bfloat16 l0=__float2bfloat16(v.x-__bfloat162float(h0));
  __nv_bfloat16 l1=__float2bfloat16(v.y-__bfloat162float(h1));
  __nv_bfloat16 l2=__float2bfloat16(v.z-__bfloat162float(h2));
  __nv_bfloat16 l3=__float2bfloat16(v.w-__bfloat162float(h3));
  uint2 hp, lp;
  hp.x = ((uint32_t)__bfloat16_as_ushort(h1)<<16) | __bfloat16_as_ushort(h0);
  hp.y = ((uint32_t)__bfloat16_as_ushort(h3)<<16) | __bfloat16_as_ushort(h2);
  lp.x = ((uint32_t)__bfloat16_as_ushort(l1)<<16) | __bfloat16_as_ushort(l0);
  lp.y = ((uint32_t)__bfloat16_as_ushort(l3)<<16) | __bfloat16_as_ushort(l2);
  ((uint2*)h)[i] = hp;
  ((uint2*)l)[i] = lp;
}

// ---------------------- tensor GEMM: C = A @ W (+bias)(+add) -----------------
// A hi/lo [M,K] bf16 row-major, W hi/lo [K,N] bf16 row-major.
// M,N multiples of 128; K multiple of 16.
#define NSTG   3
#define APITCH 48
#define ABYTES (128*APITCH)        // 6144
#define BBYTES 4096                // 16 rows * 256B
#define STGB   (2*ABYTES + 2*BBYTES)   // 20480
#define TG2_SMEM (NSTG*STGB)       // 61440

__global__ __launch_bounds__(256,1) void tgemm2_kernel(
    const __nv_bfloat16* __restrict__ Ah, const __nv_bfloat16* __restrict__ Al,
    const __nv_bfloat16* __restrict__ Bh, const __nv_bfloat16* __restrict__ Bl,
    const float* __restrict__ bias, const float* __restrict__ add,
    float* __restrict__ C, int M, int N, int K)
{
  extern __shared__ char smemraw[];
  uint32_t sb = smem_u32(smemraw);
  int tid = threadIdx.x, lane = tid & 31, wid = tid >> 5;
  int m0 = blockIdx.y << 7, n0 = blockIdx.x << 7;
  int warp_m = (wid >> 2) << 6, warp_n = (wid & 3) << 5;
  int T = K >> 4;

  // per-thread cp.async indices (1024 16B chunks/stage, 4 per thread)
  int am = tid >> 1, ac = tid & 1;
  const __nv_bfloat16* agh = Ah + (size_t)(m0+am)*K + ac*8;
  const __nv_bfloat16* agl = Al + (size_t)(m0+am)*K + ac*8;
  uint32_t adst = am*APITCH + ac*16;
  int bk = tid >> 4, bc = tid & 15;
  const __nv_bfloat16* bgh = Bh + (size_t)bk*N + n0 + bc*8;
  const __nv_bfloat16* bgl = Bl + (size_t)bk*N + n0 + bc*8;
  uint32_t bdst = bk*256 + ((uint32_t)(bc ^ (bk & 7)) << 4);

  #define LOAD_STAGE(t, s) do { \
    uint32_t so_ = sb + (uint32_t)(s)*STGB; \
    int k0e_ = (t) << 4; \
    cpa16(so_ + adst,                     agh + k0e_); \
    cpa16(so_ + ABYTES + adst,            agl + k0e_); \
    cpa16(so_ + 2*ABYTES + bdst,          bgh + (size_t)k0e_*N); \
    cpa16(so_ + 2*ABYTES + BBYTES + bdst, bgl + (size_t)k0e_*N); \
    CP_COMMIT; \
  } while(0)

  float acc[4][4][4];
  #pragma unroll
  for (int i=0;i<4;i++)
    #pragma unroll
    for (int j=0;j<4;j++)
      #pragma unroll
      for (int k=0;k<4;k++) acc[i][j][k] = 0.f;

  LOAD_STAGE(0, 0);
  LOAD_STAGE(1, 1);

  // fragment smem addresses
  int arow = warp_m + ((lane>>3)&1)*8 + (lane&7);
  uint32_t aoff = (uint32_t)arow*APITCH + (uint32_t)(lane>>4)*16;
  int kk = lane & 15;

  for (int t=0; t<T; ++t){
    if (t+1 < T) { CP_WAIT1; } else { CP_WAIT0; }
    __syncthreads();
    if (t+2 < T) LOAD_STAGE(t+2, (t+2)%NSTG);

    uint32_t so = sb + (uint32_t)(t%NSTG)*STGB;
    uint32_t ah[4][4], alr[4][4], bh[4][2], blr[4][2];
    #pragma unroll
    for (int mt=0; mt<4; ++mt){
      uint32_t a = so + aoff + (uint32_t)mt*16*APITCH;
      LDM_X4(ah[mt][0], ah[mt][1], ah[mt][2], ah[mt][3], a);
      LDM_X4(alr[mt][0], alr[mt][1], alr[mt][2], alr[mt][3], a + ABYTES);
    }
    #pragma unroll
    for (int np=0; np<2; ++np){
      uint32_t c = (uint32_t)(warp_n>>3) + np*2 + (lane>>4);
      uint32_t phys = c ^ (uint32_t)(kk & 7);
      uint32_t a = so + 2*ABYTES + (uint32_t)kk*256 + phys*16;
      uint32_t r0,r1,r2,r3;
      LDM_X4T(r0,r1,r2,r3, a);
      bh[np*2][0]=r0; bh[np*2][1]=r1; bh[np*2+1][0]=r2; bh[np*2+1][1]=r3;
      LDM_X4T(r0,r1,r2,r3, a + BBYTES);
      blr[np*2][0]=r0; blr[np*2][1]=r1; blr[np*2+1][0]=r2; blr[np*2+1][1]=r3;
    }
    // pass 1: hi*hi
    #pragma unroll
    for (int mt=0; mt<4; ++mt)
      #pragma unroll
      for (int nt=0; nt<4; ++nt) MMA16816(acc[mt][nt], ah[mt], bh[nt]);
    // pass 2: lo*hi
    #pragma unroll
    for (int mt=0; mt<4; ++mt)
      #pragma unroll
      for (int nt=0; nt<4; ++nt) MMA16816(acc[mt][nt], alr[mt], bh[nt]);
    // pass 3: hi*lo
    #pragma unroll
    for (int mt=0; mt<4; ++mt)
      #pragma unroll
      for (int nt=0; nt<4; ++nt) MMA16816(acc[mt][nt], ah[mt], blr[nt]);
  }
  #undef LOAD_STAGE

  // epilogue
  int g = lane >> 2, c2 = (lane & 3) << 1;
  #pragma unroll
  for (int mt=0; mt<4; ++mt){
    #pragma unroll
    for (int nt=0; nt<4; ++nt){
      int r = m0 + warp_m + mt*16 + g;
      int col = n0 + warp_n + nt*8 + c2;
      size_t o0 = (size_t)r*N + col, o1 = o0 + (size_t)8*N;
      float x0=acc[mt][nt][0], x1=acc[mt][nt][1], x2=acc[mt][nt][2], x3=acc[mt][nt][3];
      if (bias){ float b0=bias[col], b1=bias[col+1]; x0+=b0; x1+=b1; x2+=b0; x3+=b1; }
      if (add){ x0+=add[o0]; x1+=add[o0+1]; x2+=add[o1]; x3+=add[o1+1]; }
      float2 v0 = make_float2(x0,x1), v1 = make_float2(x2,x3);
      *(float2*)(C+o0) = v0;
      *(float2*)(C+o1) = v1;
    }
  }
}

// ----------------------------- concat + router -----------------------------
__global__ __launch_bounds__(256) void concat_router_kernel(
    const float* __restrict__ pose, const float* __restrict__ scene,
    const float* __restrict__ f1w, const float* __restrict__ f1b,
    const float* __restrict__ f2w, const float* __restrict__ f2b,
    float* __restrict__ X, float* __restrict__ R)
{
  int t = blockIdx.x;
  int b = t >> 9, s = t & 511;
  const float* src = (s < 256) ? pose + (size_t)((b<<8)+s)*HD
                               : scene + (size_t)((b<<8)+(s-256))*HD;
  const float4* s4 = (const float4*)src;
  float4* d4 = (float4*)(X + (size_t)t*HD);
  float4 v = s4[threadIdx.x];
  d4[threadIdx.x] = v;
  float vals[4] = {v.x, v.y, v.z, v.w};
  float acc[4] = {0.f,0.f,0.f,0.f};
  int i0 = threadIdx.x * 4;
  #pragma unroll
  for (int c=0;c<4;c++){
    #pragma unroll
    for (int e=0;e<4;e++) acc[e] += vals[c] * f1w[(i0+c)*4 + e];
  }
  __shared__ float sm[8][4];
  int lane = threadIdx.x & 31, warp = threadIdx.x >> 5;
  #pragma unroll
  for (int e=0;e<4;e++){
    float a = acc[e];
    #pragma unroll
    for (int o=16;o;o>>=1) a += __shfl_down_sync(0xffffffffu, a, o);
    if (!lane) sm[warp][e] = a;
  }
  __syncthreads();
  if (threadIdx.x == 0){
    float g[4];
    #pragma unroll
    for (int e=0;e<4;e++){
      float su = f1b[e];
      #pragma unroll
      for (int w=0;w<8;w++) su += sm[w][e];
      g[e] = 0.5f * su * (1.f + erff(su * 0.70710678118654752f));
    }
    float rr[4]; float tot = 0.f;
    #pragma unroll
    for (int j=0;j<4;j++){
      float z = f2b[j];
      #pragma unroll
      for (int e=0;e<4;e++) z += g[e] * f2w[e*4 + j];
      float sg = 1.f / (1.f + expf(-z));
      rr[j] = sg; tot += sg;
    }
    tot = fmaxf(tot, 1e-8f);
    #pragma unroll
    for (int j=0;j<4;j++) R[t*4 + j] = rr[j] / tot;
  }
}

// ----------------------------- RMSNorm --------------------------------------
__global__ __launch_bounds__(256) void rms_kernel(
    const float* __restrict__ x, const float* __restrict__ w, float* __restrict__ o)
{
  __shared__ float sm[32];
  int row = blockIdx.x;
  const float* xr = x + (size_t)row*HD;
  float ss = 0.f;
  for (int i=threadIdx.x; i<HD; i+=256){ float v = xr[i]; ss += v*v; }
  float tot = blockReduceSum(ss, sm);
  float sc = rsqrtf(tot * (1.f/HD) + 1e-5f);
  float* orow = o + (size_t)row*HD;
  for (int i=threadIdx.x; i<HD; i+=256) orow[i] = xr[i] * sc * w[i];
}

// ----------------------------- fp32 GEMM (compact M) ------------------------
#define BM 128
#define BN 128
#define BK 16

__global__ __launch_bounds__(256) void gemm_kernel(
    const float* __restrict__ A, const float* __restrict__ W,
    const float* __restrict__ bias, const float* __restrict__ add,
    float* __restrict__ C, int M, int N, int K)
{
  __shared__ float As[BK][BM];
  __shared__ float Ws[BK][BN];
  int tid = threadIdx.x;
  int m0 = blockIdx.y * BM, n0 = blockIdx.x * BN;
  int tm = (tid >> 4) << 3;
  int tn = (tid & 15) << 3;
  unsigned long long acc[8][4];
  #pragma unroll
  for (int i=0;i<8;i++){
    #pragma unroll
    for (int j=0;j<4;j++) acc[i][j] = 0ULL;
  }
  int T = K >> 4;
  int arow0 = tid >> 2,          ac0 = (tid & 3) << 2;
  int arow1 = (tid >> 2) + 64,   ac1 = ac0;
  int wrow0 = tid >> 5,          wc0 = (tid & 31) << 2;
  int wrow1 = (tid >> 5) + 8,    wc1 = wc0;

  float4 ra0, ra1, rw0, rw1;
  const float4 z4 = make_float4(0.f,0.f,0.f,0.f);
  {
    int g0 = m0 + arow0, g1 = m0 + arow1;
    ra0 = (g0 < M) ? *(const float4*)(A + (size_t)g0*K + ac0) : z4;
    ra1 = (g1 < M) ? *(const float4*)(A + (size_t)g1*K + ac1) : z4;
    rw0 = *(const float4*)(W + (size_t)wrow0*N + n0 + wc0);
    rw1 = *(const float4*)(W + (size_t)wrow1*N + n0 + wc1);
  }
  for (int t=0; t<T; ++t){
    As[ac0+0][arow0]=ra0.x; As[ac0+1][arow0]=ra0.y; As[ac0+2][arow0]=ra0.z; As[ac0+3][arow0]=ra0.w;
    As[ac1+0][arow1]=ra1.x; As[ac1+1][arow1]=ra1.y; As[ac1+2][arow1]=ra1.z; As[ac1+3][arow1]=ra1.w;
    *(float4*)&Ws[wrow0][wc0] = rw0;
    *(float4*)&Ws[wrow1][wc1] = rw1;
    __syncthreads();
    if (t+1 < T){
      int kb = (t+1) << 4;
      int g0 = m0 + arow0, g1 = m0 + arow1;
      ra0 = (g0 < M) ? *(const float4*)(A + (size_t)g0*K + kb + ac0) : z4;
      ra1 = (g1 < M) ? *(const float4*)(A + (size_t)g1*K + kb + ac1) : z4;
      rw0 = *(const float4*)(W + (size_t)(kb+wrow0)*N + n0 + wc0);
      rw1 = *(const float4*)(W + (size_t)(kb+wrow1)*N + n0 + wc1);
    }
    #pragma unroll
    for (int kk=0; kk<BK; ++kk){
      float4 a0 = *(const float4*)&As[kk][tm];
      float4 a1 = *(const float4*)&As[kk][tm+4];
      const unsigned long long* wp = (const unsigned long long*)&Ws[kk][tn];
      unsigned long long b0 = wp[0], b1 = wp[1], b2 = wp[2], b3 = wp[3];
      unsigned long long p;
      #define ROWF(i, av) { p = pk2(av); ffma2(acc[i][0],p,b0); ffma2(acc[i][1],p,b1); \
                            ffma2(acc[i][2],p,b2); ffma2(acc[i][3],p,b3); }
      ROWF(0, a0.x) ROWF(1, a0.y) ROWF(2, a0.z) ROWF(3, a0.w)
      ROWF(4, a1.x) ROWF(5, a1.y) ROWF(6, a1.z) ROWF(7, a1.w)
      #undef ROWF
    }
    __syncthreads();
  }
  #pragma unroll
  for (int i=0;i<8;i++){
    int row = m0 + tm + i;
    if (row >= M) continue;
    size_t rb = (size_t)row * N;
    #pragma unroll
    for (int j=0;j<4;j++){
      F2U v; v.u = acc[i][j];
      int col = n0 + tn + j*2;
      float e0 = v.f.x, e1 = v.f.y;
      if (bias){ e0 += bias[col]; e1 += bias[col+1]; }
      if (add){ e0 += add[rb+col]; e1 += add[rb+col+1]; }
      C[rb+col] = e0; C[rb+col+1] = e1;
    }
  }
}

// ----------------------------- attention ------------------------------------
#define QS 65
#define ATTN_SMEM ((32*QS + 64*QS + 32*512) * 4)

__global__ __launch_bounds__(256) void attn_kernel(
    const float* __restrict__ Q, const float* __restrict__ K,
    const float* __restrict__ V, float* __restrict__ O, int q_per_b)
{
  extern __shared__ float smem[];
  float* Qs = smem;              // 32*QS
  float* KV = Qs + 32*QS;        // 64*QS
  float* S  = KV + 64*QS;        // 32*512
  int tid = threadIdx.x;
  int bh = blockIdx.y; int b = bh >> 4, h = bh & 15;
  int q0 = blockIdx.x * 32;
  #pragma unroll
  for (int i=0;i<8;i++){
    int idx = tid + i*256; int qi = idx >> 6, d = idx & 63;
    float v = 0.f;
    if (q0 + qi < q_per_b) v = Q[(size_t)(b*q_per_b + q0 + qi)*HD + h*64 + d];
    Qs[qi*QS + d] = v;
  }
  __syncthreads();
  int sgrp = tid & 15, qgrp = tid >> 4;
  for (int kt=0; kt<8; ++kt){
    #pragma unroll
    for (int i=0;i<16;i++){
      int idx = tid + i*256; int sk = idx >> 6, d = idx & 63;
      KV[sk*QS + d] = K[(size_t)(b*512 + kt*64 + sk)*HD + h*64 + d];
    }
    __syncthreads();
    float a00=0,a01=0,a02=0,a03=0,a10=0,a11=0,a12=0,a13=0;
    #pragma unroll 8
    for (int d=0; d<64; ++d){
      float q0v = Qs[(qgrp*2  )*QS + d];
      float q1v = Qs[(qgrp*2+1)*QS + d];
      float k0 = KV[(sgrp*4  )*QS + d];
      float k1 = KV[(sgrp*4+1)*QS + d];
      float k2 = KV[(sgrp*4+2)*QS + d];
      float k3 = KV[(sgrp*4+3)*QS + d];
      a00 += q0v*k0; a01 += q0v*k1; a02 += q0v*k2; a03 += q0v*k3;
      a10 += q1v*k0; a11 += q1v*k1; a12 += q1v*k2; a13 += q1v*k3;
    }
    int r0 = (qgrp*2)*512 + kt*64 + sgrp*4, r1 = r0 + 512;
    S[r0+0]=a00*0.125f; S[r0+1]=a01*0.125f; S[r0+2]=a02*0.125f; S[r0+3]=a03*0.125f;
    S[r1+0]=a10*0.125f; S[r1+1]=a11*0.125f; S[r1+2]=a12*0.125f; S[r1+3]=a13*0.125f;
    __syncthreads();
  }
  int lane = tid & 31, warp = tid >> 5;
  for (int rr=0; rr<4; ++rr){
    int qi = warp*4 + rr;
    float m = -1e30f;
    for (int j=lane; j<512; j+=32) m = fmaxf(m, S[qi*512 + j]);
    #pragma unroll
    for (int o=16;o;o>>=1) m = fmaxf(m, __shfl_xor_sync(0xffffffffu, m, o));
    float ssum = 0.f;
    for (int j=lane; j<512; j+=32){ float e = __expf(S[qi*512+j] - m); S[qi*512+j] = e; ssum += e; }
    #pragma unroll
    for (int o=16;o;o>>=1) ssum += __shfl_xor_sync(0xffffffffu, ssum, o);
    float inv = 1.f / ssum;
    for (int j=lane; j<512; j+=32) S[qi*512+j] *= inv;
  }
  __syncthreads();
  int dgrp = sgrp;
  float o00=0,o01=0,o02=0,o03=0,o10=0,o11=0,o12=0,o13=0;
  for (int kt=0; kt<8; ++kt){
    #pragma unroll
    for (int i=0;i<16;i++){
      int idx = tid + i*256; int sk = idx >> 6, d = idx & 63;
      KV[sk*QS + d] = V[(size_t)(b*512 + kt*64 + sk)*HD + h*64 + d];
    }
    __syncthreads();
    #pragma unroll 4
    for (int sk=0; sk<64; ++sk){
      float p0 = S[(qgrp*2  )*512 + kt*64 + sk];
      float p1 = S[(qgrp*2+1)*512 + kt*64 + sk];
      float v0 = KV[sk*QS + dgrp*4+0];
      float v1 = KV[sk*QS + dgrp*4+1];
      float v2 = KV[sk*QS + dgrp*4+2];
      float v3 = KV[sk*QS + dgrp*4+3];
      o00 += p0*v0; o01 += p0*v1; o02 += p0*v2; o03 += p0*v3;
      o10 += p1*v0; o11 += p1*v1; o12 += p1*v2; o13 += p1*v3;
    }
    __syncthreads();
  }
  {
    int qi = qgrp*2;
    if (q0 + qi < q_per_b){
      size_t base = (size_t)(b*q_per_b + q0 + qi)*HD + h*64 + dgrp*4;
      O[base+0]=o00; O[base+1]=o01; O[base+2]=o02; O[base+3]=o03;
    }
    qi = qgrp*2 + 1;
    if (q0 + qi < q_per_b){
      size_t base = (size_t)(b*q_per_b + q0 + qi)*HD + h*64 + dgrp*4;
      O[base+0]=o10; O[base+1]=o11; O[base+2]=o12; O[base+3]=o13;
    }
  }
}

// ----------------------------- small kernels --------------------------------
__global__ __launch_bounds__(256) void silu_mul_kernel(float* __restrict__ u,
                                                       const float* __restrict__ t, int n)
{
  int i = blockIdx.x * 256 + threadIdx.x;
  if (i < n){ float x = u[i]; u[i] = (x / (1.f + __expf(-x))) * t[i]; }
}

__global__ __launch_bounds__(256) void gather240_kernel(const float* __restrict__ in,
                                                        float* __restrict__ out)
{
  int j = blockIdx.x;
  int gr = (j/30)*512 + (j%30);
  const float4* s = (const float4*)(in + (size_t)gr*HD);
  float4* d = (float4*)(out + (size_t)j*HD);
  d[threadIdx.x] = s[threadIdx.x];
}

__global__ __launch_bounds__(256) void combine240_kernel(const float* __restrict__ h,
    const float* __restrict__ r, int e, int first, float* __restrict__ C)
{
  int j = blockIdx.x;
  int gr = (j/30)*512 + (j%30);
  float w = r[gr*4 + e];
  for (int c=threadIdx.x; c<HD; c+=256){
    float v = h[(size_t)j*HD + c] * w;
    C[(size_t)j*HD + c] = first ? v : C[(size_t)j*HD + c] + v;
  }
}

__global__ __launch_bounds__(256) void layernorm_kernel(const float* __restrict__ y,
    const float* __restrict__ w, const float* __restrict__ bb, float* __restrict__ out)
{
  __shared__ float sm[32];
  int row = blockIdx.x;
  const float* yr = y + (size_t)row*HD;
  float s = 0.f, sq = 0.f;
  for (int i=threadIdx.x; i<HD; i+=256){ float v = yr[i]; s += v; sq += v*v; }
  float ts = blockReduceSum(s, sm);
  float tq = blockReduceSum(sq, sm);
  float mu = ts * (1.f/HD);
  float var = tq * (1.f/HD) - mu*mu;
  float inv = rsqrtf(var + 1e-5f);
  float* orow = out + (size_t)row*HD;
  for (int i=threadIdx.x; i<HD; i+=256) orow[i] = (yr[i] - mu) * inv * w[i] + bb[i];
}

// ----------------------------- host orchestration ---------------------------
extern "C" void kernel_launch(void* const* d_in, const int* in_sizes, int n_in,
                              void* d_out, int out_size)
{
  const float* pose = (const float*)d_in[0];
  const float* scene= (const float*)d_in[1];
  const float* rf1w = (const float*)d_in[2];
  const float* rf1b = (const float*)d_in[3];
  const float* rf2w = (const float*)d_in[4];
  const float* rf2b = (const float*)d_in[5];
  const float* anw  = (const float*)d_in[6];
  const float* wq   = (const float*)d_in[7];
  const float* wqb  = (const float*)d_in[8];
  const float* wk   = (const float*)d_in[9];
  const float* wkb  = (const float*)d_in[10];
  const float* wv   = (const float*)d_in[11];
  const float* wvb  = (const float*)d_in[12];
  const float* wo   = (const float*)d_in[13];
  const float* wob  = (const float*)d_in[14];
  const float* fnw  = (const float*)d_in[15];
  const float* w1   = (const float*)d_in[16];
  const float* w2   = (const float*)d_in[17];
  const float* w3   = (const float*)d_in[18];
  const float* pw   = (const float*)d_in[19];
  const float* pb   = (const float*)d_in[20];
  const float* lnw  = (const float*)d_in[21];
  const float* lnb  = (const float*)d_in[22];

  float *X,*R,*H,*H2,*XN,*Q,*K,*V,*O,*U,*T;
  float *cXN,*cH,*cQ,*cO,*cH2,*cU,*cT,*cF,*C,*Y;
  cudaGetSymbolAddress((void**)&X,  g_X);
  cudaGetSymbolAddress((void**)&R,  g_R);
  cudaGetSymbolAddress((void**)&H,  g_H);
  cudaGetSymbolAddress((void**)&H2, g_H2);
  cudaGetSymbolAddress((void**)&XN, g_XN);
  cudaGetSymbolAddress((void**)&Q,  g_Q);
  cudaGetSymbolAddress((void**)&K,  g_K);
  cudaGetSymbolAddress((void**)&V,  g_V);
  cudaGetSymbolAddress((void**)&O,  g_O);
  cudaGetSymbolAddress((void**)&U,  g_U);
  cudaGetSymbolAddress((void**)&T,  g_T);
  cudaGetSymbolAddress((void**)&cXN,g_cXN);
  cudaGetSymbolAddress((void**)&cH, g_cH);
  cudaGetSymbolAddress((void**)&cQ, g_cQ);
  cudaGetSymbolAddress((void**)&cO, g_cO);
  cudaGetSymbolAddress((void**)&cH2,g_cH2);
  cudaGetSymbolAddress((void**)&cU, g_cU);
  cudaGetSymbolAddress((void**)&cT, g_cT);
  cudaGetSymbolAddress((void**)&cF, g_cF);
  cudaGetSymbolAddress((void**)&C,  g_C);
  cudaGetSymbolAddress((void**)&Y,  g_Y);

  __nv_bfloat16 *wqh,*wql,*wkh,*wkl,*wvh,*wvl,*woh,*wol;
  __nv_bfloat16 *w1h,*w1l,*w2h,*w2l,*w3h,*w3l,*Abh,*Abl;
  cudaGetSymbolAddress((void**)&wqh, g_wq_h); cudaGetSymbolAddress((void**)&wql, g_wq_l);
  cudaGetSymbolAddress((void**)&wkh, g_wk_h); cudaGetSymbolAddress((void**)&wkl, g_wk_l);
  cudaGetSymbolAddress((void**)&wvh, g_wv_h); cudaGetSymbolAddress((void**)&wvl, g_wv_l);
  cudaGetSymbolAddress((void**)&woh, g_wo_h); cudaGetSymbolAddress((void**)&wol, g_wo_l);
  cudaGetSymbolAddress((void**)&w1h, g_w1_h); cudaGetSymbolAddress((void**)&w1l, g_w1_l);
  cudaGetSymbolAddress((void**)&w2h, g_w2_h); cudaGetSymbolAddress((void**)&w2l, g_w2_l);
  cudaGetSymbolAddress((void**)&w3h, g_w3_h); cudaGetSymbolAddress((void**)&w3l, g_w3_l);
  cudaGetSymbolAddress((void**)&Abh, g_Ahb);  cudaGetSymbolAddress((void**)&Abl, g_Alb);

  cudaFuncSetAttribute(attn_kernel, cudaFuncAttributeMaxDynamicSharedMemorySize, ATTN_SMEM);
  cudaFuncSetAttribute(tgemm2_kernel, cudaFuncAttributeMaxDynamicSharedMemorySize, TG2_SMEM);

  // ---- weight hi/lo conversion (once per launch) ----
  cvt_kernel<<<WQN/4/256, 256>>>(wq, wqh, wql, WQN/4);
  cvt_kernel<<<WQN/4/256, 256>>>(wk, wkh, wkl, WQN/4);
  cvt_kernel<<<WQN/4/256, 256>>>(wv, wvh, wvl, WQN/4);
  cvt_kernel<<<WQN/4/256, 256>>>(wo, woh, wol, WQN/4);
  cvt_kernel<<<WFN/4/256, 256>>>(w1, w1h, w1l, WFN/4);
  cvt_kernel<<<WFN/4/256, 256>>>(w2, w2h, w2l, WFN/4);
  cvt_kernel<<<WFN/4/256, 256>>>(w3, w3h, w3l, WFN/4);

  concat_router_kernel<<<NTOK, 256>>>(pose, scene, rf1w, rf1b, rf2w, rf2b, X, R);

  const size_t HH = (size_t)HD*HD;
  const size_t HHF = (size_t)HD*HF;
  dim3 tFull1024(HD/128, NTOK/128);   // (8, 32)
  dim3 tFullHF(HF/128, NTOK/128);     // (22, 32)
  dim3 gCmp1024(8, 2);                // M=240  N=1024
  dim3 gCmpHF(22, 2);                 // M=240  N=2816
  const int N4_H  = NTOK*HD/4;
  const int N4_HF = NTOK*HF/4;

  for (int e=0; e<4; ++e){
    cudaMemcpyAsync(H, X, (size_t)NTOK*HD*sizeof(float), cudaMemcpyDeviceToDevice, 0);

    // ---- layer 0 (full, tensor MMA) ----
    int el = e*2 + 0;
    rms_kernel<<<NTOK, 256>>>(H, anw + (size_t)el*HD, XN);
    cvt_kernel<<<N4_H/256, 256>>>(XN, Abh, Abl, N4_H);
    tgemm2_kernel<<<tFull1024, 256, TG2_SMEM>>>(Abh, Abl, wqh + el*HH, wql + el*HH, wqb + (size_t)el*HD, nullptr, Q, NTOK, HD, HD);
    tgemm2_kernel<<<tFull1024, 256, TG2_SMEM>>>(Abh, Abl, wkh + el*HH, wkl + el*HH, wkb + (size_t)el*HD, nullptr, K, NTOK, HD, HD);
    tgemm2_kernel<<<tFull1024, 256, TG2_SMEM>>>(Abh, Abl, wvh + el*HH, wvl + el*HH, wvb + (size_t)el*HD, nullptr, V, NTOK, HD, HD);
    attn_kernel<<<dim3(16,128), 256, ATTN_SMEM>>>(Q, K, V, O, 512);
    cvt_kernel<<<N4_H/256, 256>>>(O, Abh, Abl, N4_H);
    tgemm2_kernel<<<tFull1024, 256, TG2_SMEM>>>(Abh, Abl, woh + el*HH, wol + el*HH, wob + (size_t)el*HD, H, H2, NTOK, HD, HD);
    rms_kernel<<<NTOK, 256>>>(H2, fnw + (size_t)el*HD, XN);
    cvt_kernel<<<N4_H/256, 256>>>(XN, Abh, Abl, N4_H);
    tgemm2_kernel<<<tFullHF, 256, TG2_SMEM>>>(Abh, Abl, w1h + el*HHF, w1l + el*HHF, nullptr, nullptr, U, NTOK, HF, HD);
    tgemm2_kernel<<<tFullHF, 256, TG2_SMEM>>>(Abh, Abl, w3h + el*HHF, w3l + el*HHF, nullptr, nullptr, T, NTOK, HF, HD);
    silu_mul_kernel<<<(NTOK*HF + 255)/256, 256>>>(U, T, NTOK*HF);
    cvt_kernel<<<N4_HF/256, 256>>>(U, Abh, Abl, N4_HF);
    tgemm2_kernel<<<tFull1024, 256, TG2_SMEM>>>(Abh, Abl, w2h + el*HHF, w2l + el*HHF, nullptr, H2, H, NTOK, HD, HF);

    // ---- layer 1 (K/V full tensor, rest compact 240 rows fp32) ----
    el = e*2 + 1;
    rms_kernel<<<NTOK, 256>>>(H, anw + (size_t)el*HD, XN);
    cvt_kernel<<<N4_H/256, 256>>>(XN, Abh, Abl, N4_H);
    tgemm2_kernel<<<tFull1024, 256, TG2_SMEM>>>(Abh, Abl, wkh + el*HH, wkl + el*HH, wkb + (size_t)el*HD, nullptr, K, NTOK, HD, HD);
    tgemm2_kernel<<<tFull1024, 256, TG2_SMEM>>>(Abh, Abl, wvh + el*HH, wvl + el*HH, wvb + (size_t)el*HD, nullptr, V, NTOK, HD, HD);
    gather240_kernel<<<NKEEP, 256>>>(XN, cXN);
    gather240_kernel<<<NKEEP, 256>>>(H, cH);
    gemm_kernel<<<gCmp1024, 256>>>(cXN, wq + el*HH, wqb + (size_t)el*HD, nullptr, cQ, NKEEP, HD, HD);
    attn_kernel<<<dim3(1,128), 256, ATTN_SMEM>>>(cQ, K, V, cO, 30);
    gemm_kernel<<<gCmp1024, 256>>>(cO, wo + el*HH, wob + (size_t)el*HD, cH, cH2, NKEEP, HD, HD);
    rms_kernel<<<NKEEP, 256>>>(cH2, fnw + (size_t)el*HD, cXN);
    gemm_kernel<<<gCmpHF, 256>>>(cXN, w1 + el*HHF, nullptr, nullptr, cU, NKEEP, HF, HD);
    gemm_kernel<<<gCmpHF, 256>>>(cXN, w3 + el*HHF, nullptr, nullptr, cT, NKEEP, HF, HD);
    silu_mul_kernel<<<(NKEEP*HF + 255)/256, 256>>>(cU, cT, NKEEP*HF);
    gemm_kernel<<<gCmp1024, 256>>>(cU, w2 + el*HHF, nullptr, cH2, cF, NKEEP, HD, HF);
    combine240_kernel<<<NKEEP, 256>>>(cF, R, e, (e==0) ? 1 : 0, C);
  }

  // ---- final projection + LayerNorm ----
  gemm_kernel<<<gCmp1024, 256>>>(C, pw, pb, nullptr, Y, NKEEP, HD, HD);
  layernorm_kernel<<<NKEEP, 256>>>(Y, lnw, lnb, (float*)d_out);
}